// round 7
// baseline (speedup 1.0000x reference)
#include <cuda_runtime.h>
#include <stdint.h>

#define B_  2
#define S_  2048
#define D_  1024
#define H_  16
#define DK_ 64
#define N_  (B_ * S_)            // 4096
#define BH_ (B_ * H_)            // 32

// ---------------- scratch (static device globals) ---------------------------
// layout [b][h][s][dk]
__device__ float g_qp[BH_ * S_ * DK_];   // X @ WQ * scale   (key role)
__device__ float g_kp[BH_ * S_ * DK_];   // X @ WK           (query role)
__device__ float g_vp[BH_ * S_ * DK_];   // X @ WV
__device__ float g_ao[BH_ * S_ * DK_];   // attention output

// ---------------- tf32 helpers ----------------------------------------------
__device__ __forceinline__ uint32_t f2tf(float x) {
    uint32_t u; asm("cvt.rna.tf32.f32 %0, %1;" : "=r"(u) : "f"(x)); return u;
}
__device__ __forceinline__ float tf(float x) { return __uint_as_float(f2tf(x)); }

// D += A(16x8) @ B(8x8), tf32 inputs, fp32 accum, accumulate in place.
__device__ __forceinline__ void mma8(float* d, const uint32_t* a, const uint32_t* b) {
    asm volatile("mma.sync.aligned.m16n8k8.row.col.f32.tf32.tf32.f32 "
                 "{%0,%1,%2,%3}, {%4,%5,%6,%7}, {%8,%9}, {%0,%1,%2,%3};\n"
                 : "+f"(d[0]), "+f"(d[1]), "+f"(d[2]), "+f"(d[3])
                 : "r"(a[0]), "r"(a[1]), "r"(a[2]), "r"(a[3]),
                   "r"(b[0]), "r"(b[1]));
}

__device__ __forceinline__ void cpasync16(uint32_t smem_dst, const void* gptr) {
    asm volatile("cp.async.cg.shared.global [%0], [%1], 16;\n"
                 :: "r"(smem_dst), "l"(gptr));
}
__device__ __forceinline__ void cpcommit() {
    asm volatile("cp.async.commit_group;\n");
}
__device__ __forceinline__ void cpwait0() {
    asm volatile("cp.async.wait_group 0;\n");
}

// ---------------- GEMM smem geometry (proj / out-proj) -----------------------
#define AS_W   36                       // A tile row stride (32 + 4)
#define BS_W   136                      // B tile row stride (128 + 8)
#define A_FL   (128 * AS_W)             // floats per A stage
#define B_FL   (32 * BS_W)              // floats per B stage
#define STG_FL (A_FL + B_FL)
#define PROJ_SMEM_BYTES (2 * STG_FL * 4)

// ============================================================================
// Kernel 1: QKV projection (tf32 mma, cp.async double-buffered).
// Block tile 128x128, k-tile 32. 8 warps: 2(M) x 4(N), warp tile 64x32.
// ============================================================================
__global__ void __launch_bounds__(256, 2)
proj_qkv_mma(const float* __restrict__ X,
             const float* __restrict__ WQ,
             const float* __restrict__ WK,
             const float* __restrict__ WV)
{
    extern __shared__ float dsm[];
    const int mat = blockIdx.z;
    const float* __restrict__ W = (mat == 0) ? WQ : (mat == 1) ? WK : WV;
    float* __restrict__ C = (mat == 0) ? g_qp : (mat == 1) ? g_kp : g_vp;
    const float alpha = (mat == 0) ? 0.125f : 1.0f;   // 1/sqrt(64)

    const int row0 = blockIdx.y * 128;
    const int col0 = blockIdx.x * 128;
    const int tid  = threadIdx.x;
    const int lane = tid & 31;
    const int wid  = tid >> 5;
    const int wm   = (wid & 1) * 64;
    const int wn   = (wid >> 1) * 32;
    const int gr   = lane >> 2;
    const int tg   = lane & 3;

    const uint32_t sbase = (uint32_t)__cvta_generic_to_shared(dsm);

    // per-thread chunk indices (4 A chunks + 4 B chunks of 16B)
    int ar[4], ac[4], br[4], bc[4];
#pragma unroll
    for (int i = 0; i < 4; i++) {
        int f = tid + i * 256;
        ar[i] = f >> 3;  ac[i] = (f & 7) * 4;
        br[i] = f >> 5;  bc[i] = (f & 31) * 4;
    }

    auto issue = [&](int stage, int k0) {
        const uint32_t sa = sbase + (uint32_t)(stage * STG_FL) * 4u;
        const uint32_t sb = sa + (uint32_t)A_FL * 4u;
#pragma unroll
        for (int i = 0; i < 4; i++)
            cpasync16(sa + (uint32_t)(ar[i] * AS_W + ac[i]) * 4u,
                      X + (row0 + ar[i]) * D_ + k0 + ac[i]);
#pragma unroll
        for (int i = 0; i < 4; i++)
            cpasync16(sb + (uint32_t)(br[i] * BS_W + bc[i]) * 4u,
                      W + (k0 + br[i]) * D_ + col0 + bc[i]);
        cpcommit();
    };

    float acc[4][4][4];
#pragma unroll
    for (int i = 0; i < 4; i++)
#pragma unroll
        for (int j = 0; j < 4; j++)
#pragma unroll
            for (int r = 0; r < 4; r++) acc[i][j][r] = 0.0f;

    issue(0, 0);

    const int NK = D_ / 32;   // 32 k-steps
    for (int kstep = 0; kstep < NK; kstep++) {
        const int stage = kstep & 1;
        float* Ab = dsm + stage * STG_FL;
        float* Bb = Ab + A_FL;

        cpwait0();
        __syncthreads();                       // all warps done with prev mma

        if (kstep + 1 < NK) issue(stage ^ 1, (kstep + 1) * 32);

        // convert current stage in place (fp32 -> tf32 RNA)
#pragma unroll
        for (int i = 0; i < 4; i++) {
            float4* p = (float4*)(Ab + ar[i] * AS_W + ac[i]);
            float4 v = *p;
            v.x = tf(v.x); v.y = tf(v.y); v.z = tf(v.z); v.w = tf(v.w);
            *p = v;
        }
#pragma unroll
        for (int i = 0; i < 4; i++) {
            float4* p = (float4*)(Bb + br[i] * BS_W + bc[i]);
            float4 v = *p;
            v.x = tf(v.x); v.y = tf(v.y); v.z = tf(v.z); v.w = tf(v.w);
            *p = v;
        }
        __syncthreads();

#pragma unroll
        for (int ks = 0; ks < 4; ks++) {
            const int kk = ks * 8;
            uint32_t a[4][4], b[4][2];
#pragma unroll
            for (int mf = 0; mf < 4; mf++) {
                int m = wm + mf * 16;
                a[mf][0] = __float_as_uint(Ab[(m + gr) * AS_W + kk + tg]);
                a[mf][1] = __float_as_uint(Ab[(m + gr + 8) * AS_W + kk + tg]);
                a[mf][2] = __float_as_uint(Ab[(m + gr) * AS_W + kk + tg + 4]);
                a[mf][3] = __float_as_uint(Ab[(m + gr + 8) * AS_W + kk + tg + 4]);
            }
#pragma unroll
            for (int nf = 0; nf < 4; nf++) {
                int n = wn + nf * 8 + gr;
                b[nf][0] = __float_as_uint(Bb[(kk + tg) * BS_W + n]);
                b[nf][1] = __float_as_uint(Bb[(kk + tg + 4) * BS_W + n]);
            }
#pragma unroll
            for (int mf = 0; mf < 4; mf++)
#pragma unroll
                for (int nf = 0; nf < 4; nf++)
                    mma8(acc[mf][nf], a[mf], b[nf]);
        }
    }

    // epilogue: scatter into [b][h][s][dk]
#pragma unroll
    for (int mf = 0; mf < 4; mf++) {
#pragma unroll
        for (int rr = 0; rr < 2; rr++) {
            int r = row0 + wm + mf * 16 + gr + rr * 8;
            int b = r >> 11, s = r & (S_ - 1);
#pragma unroll
            for (int nf = 0; nf < 4; nf++) {
                int c = col0 + wn + nf * 8 + 2 * tg;
                int h = c >> 6, dk = c & 63;
                float2 v;
                v.x = acc[mf][nf][rr * 2 + 0] * alpha;
                v.y = acc[mf][nf][rr * 2 + 1] * alpha;
                *(float2*)&C[((b * H_ + h) * S_ + s) * DK_ + dk] = v;
            }
        }
    }
}

// ============================================================================
// Kernel 2: causal flash attention, tf32 mma, register-resident softmax.
// 128 threads (4 warps); warp w owns query rows [16w,16w+16) x all 64 keys.
// P never leaves registers (quad-shfl C->A fragment transform).
// ============================================================================
#define MASKV   (-3.0e38f)
#define QKW     68                          // Qs/Ks row stride  (== 4 mod 32)
#define VW      72                          // Vs row stride     (== 8 mod 32)
#define QS_FL   (64 * QKW)
#define KS_FL   (64 * QKW)
#define VS_FL   (64 * VW)
#define ATTN_SMEM_BYTES ((QS_FL + KS_FL + VS_FL) * 4)

__global__ void __launch_bounds__(128)
attn_mma()
{
    extern __shared__ float dsm[];
    float* Qs = dsm;                 // [64][QKW]
    float* Ks = dsm + QS_FL;         // [64][QKW]
    float* Vs = dsm + QS_FL + KS_FL; // [64][VW]

    const int bh = blockIdx.x;
    const int qt = (gridDim.y - 1) - blockIdx.y;   // heavy tiles first
    const float* __restrict__ Kp = g_qp + bh * S_ * DK_;  // key role (pre-scaled)
    const float* __restrict__ Qp = g_kp + bh * S_ * DK_;  // query role
    const float* __restrict__ Vp = g_vp + bh * S_ * DK_;
    float* __restrict__ Op = g_ao + bh * S_ * DK_;

    const int t    = threadIdx.x;
    const int lane = t & 31;
    const int wid  = t >> 5;
    const int gr   = lane >> 2;
    const int tg   = lane & 3;
    const int wr   = wid * 16;          // warp's query-row base within tile

    // stage Q tile (64x64), tf32-rounded
#pragma unroll
    for (int i = 0; i < 8; i++) {
        int f = t + i * 128;
        int r = f >> 4, c = (f & 15) * 4;
        float4 v = *(const float4*)(Qp + (qt * 64 + r) * DK_ + c);
        float* q = Qs + r * QKW + c;
        q[0] = tf(v.x); q[1] = tf(v.y); q[2] = tf(v.z); q[3] = tf(v.w);
    }
    __syncthreads();

    // preload Q a-fragments (stable across all key tiles)
    uint32_t qa[8][4];
#pragma unroll
    for (int ks = 0; ks < 8; ks++) {
        const int kk = ks * 8;
        qa[ks][0] = __float_as_uint(Qs[(wr + gr) * QKW + kk + tg]);
        qa[ks][1] = __float_as_uint(Qs[(wr + gr + 8) * QKW + kk + tg]);
        qa[ks][2] = __float_as_uint(Qs[(wr + gr) * QKW + kk + tg + 4]);
        qa[ks][3] = __float_as_uint(Qs[(wr + gr + 8) * QKW + kk + tg + 4]);
    }

    float o[8][4];
#pragma unroll
    for (int nf = 0; nf < 8; nf++)
#pragma unroll
        for (int r = 0; r < 4; r++) o[nf][r] = 0.0f;

    float m0 = MASKV, m1 = MASKV, l0 = 0.0f, l1 = 0.0f;
    const int ri0 = qt * 64 + wr + gr;
    const int ri1 = ri0 + 8;

    const int nkt = qt + 1;
    for (int kt = 0; kt < nkt; kt++) {
        __syncthreads();   // prev iter done reading Ks/Vs
        // stage K and V tiles (64x64 each)
#pragma unroll
        for (int i = 0; i < 8; i++) {
            int f = t + i * 128;
            int r = f >> 4, c = (f & 15) * 4;
            float4 kv = *(const float4*)(Kp + (kt * 64 + r) * DK_ + c);
            float* kd = Ks + r * QKW + c;
            kd[0] = tf(kv.x); kd[1] = tf(kv.y); kd[2] = tf(kv.z); kd[3] = tf(kv.w);
            float4 vv = *(const float4*)(Vp + (kt * 64 + r) * DK_ + c);
            float* vd = Vs + r * VW + c;
            vd[0] = tf(vv.x); vd[1] = tf(vv.y); vd[2] = tf(vv.z); vd[3] = tf(vv.w);
        }
        __syncthreads();

        // ---- S = Q @ K^T : warp computes 16 x 64 ----
        float sc[8][4];
#pragma unroll
        for (int nf = 0; nf < 8; nf++)
#pragma unroll
            for (int r = 0; r < 4; r++) sc[nf][r] = 0.0f;

#pragma unroll
        for (int ks = 0; ks < 8; ks++) {
            const int kk = ks * 8;
#pragma unroll
            for (int nf = 0; nf < 8; nf++) {
                uint32_t b[2];
                int n = nf * 8 + gr;
                b[0] = __float_as_uint(Ks[n * QKW + kk + tg]);
                b[1] = __float_as_uint(Ks[n * QKW + kk + tg + 4]);
                mma8(sc[nf], qa[ks], b);
            }
        }

        // ---- causal mask (diagonal tile only) ----
        if (kt == qt) {
#pragma unroll
            for (int nf = 0; nf < 8; nf++) {
                int c0 = kt * 64 + nf * 8 + 2 * tg;
                if (c0 > ri0)     sc[nf][0] = MASKV;
                if (c0 + 1 > ri0) sc[nf][1] = MASKV;
                if (c0 > ri1)     sc[nf][2] = MASKV;
                if (c0 + 1 > ri1) sc[nf][3] = MASKV;
            }
        }

        // ---- register softmax (rows gr / gr+8; quad-shfl reductions) ----
        float tm0 = MASKV, tm1 = MASKV;
#pragma unroll
        for (int nf = 0; nf < 8; nf++) {
            tm0 = fmaxf(tm0, fmaxf(sc[nf][0], sc[nf][1]));
            tm1 = fmaxf(tm1, fmaxf(sc[nf][2], sc[nf][3]));
        }
        tm0 = fmaxf(tm0, __shfl_xor_sync(0xffffffffu, tm0, 1));
        tm0 = fmaxf(tm0, __shfl_xor_sync(0xffffffffu, tm0, 2));
        tm1 = fmaxf(tm1, __shfl_xor_sync(0xffffffffu, tm1, 1));
        tm1 = fmaxf(tm1, __shfl_xor_sync(0xffffffffu, tm1, 2));

        float m0n = fmaxf(m0, tm0), m1n = fmaxf(m1, tm1);
        float corr0 = __expf(m0 - m0n), corr1 = __expf(m1 - m1n);
        float ps0 = 0.0f, ps1 = 0.0f;
#pragma unroll
        for (int nf = 0; nf < 8; nf++) {
            float e0 = __expf(sc[nf][0] - m0n);
            float e1 = __expf(sc[nf][1] - m0n);
            float e2 = __expf(sc[nf][2] - m1n);
            float e3 = __expf(sc[nf][3] - m1n);
            ps0 += e0 + e1; ps1 += e2 + e3;
            sc[nf][0] = tf(e0); sc[nf][1] = tf(e1);
            sc[nf][2] = tf(e2); sc[nf][3] = tf(e3);
        }
        ps0 += __shfl_xor_sync(0xffffffffu, ps0, 1);
        ps0 += __shfl_xor_sync(0xffffffffu, ps0, 2);
        ps1 += __shfl_xor_sync(0xffffffffu, ps1, 1);
        ps1 += __shfl_xor_sync(0xffffffffu, ps1, 2);
        l0 = l0 * corr0 + ps0;  l1 = l1 * corr1 + ps1;
        m0 = m0n;  m1 = m1n;

        // rescale O
#pragma unroll
        for (int nf = 0; nf < 8; nf++) {
            o[nf][0] *= corr0; o[nf][1] *= corr0;
            o[nf][2] *= corr1; o[nf][3] *= corr1;
        }

        // ---- O += P @ V (P stays in regs: quad-shfl C->A transform) ----
        const int src1 = (lane & ~3) | (tg >> 1);
        const int src2 = src1 + 2;
        const int sel  = tg & 1;
#pragma unroll
        for (int ks = 0; ks < 8; ks++) {
            float v00 = __shfl_sync(0xffffffffu, sc[ks][0], src1);
            float v01 = __shfl_sync(0xffffffffu, sc[ks][1], src1);
            float v10 = __shfl_sync(0xffffffffu, sc[ks][2], src1);
            float v11 = __shfl_sync(0xffffffffu, sc[ks][3], src1);
            float w00 = __shfl_sync(0xffffffffu, sc[ks][0], src2);
            float w01 = __shfl_sync(0xffffffffu, sc[ks][1], src2);
            float w10 = __shfl_sync(0xffffffffu, sc[ks][2], src2);
            float w11 = __shfl_sync(0xffffffffu, sc[ks][3], src2);
            uint32_t a[4];
            a[0] = __float_as_uint(sel ? v01 : v00);
            a[1] = __float_as_uint(sel ? v11 : v10);
            a[2] = __float_as_uint(sel ? w01 : w00);
            a[3] = __float_as_uint(sel ? w11 : w10);
            const int kk = ks * 8;
#pragma unroll
            for (int nf = 0; nf < 8; nf++) {
                uint32_t b[2];
                int n = nf * 8 + gr;
                b[0] = __float_as_uint(Vs[(kk + tg) * VW + n]);
                b[1] = __float_as_uint(Vs[(kk + tg + 4) * VW + n]);
                mma8(o[nf], a, b);
            }
        }
    }

    // epilogue: normalize and store
    const float li0 = 1.0f / l0, li1 = 1.0f / l1;
#pragma unroll
    for (int nf = 0; nf < 8; nf++) {
        int c = nf * 8 + 2 * tg;
        float2 v0, v1;
        v0.x = o[nf][0] * li0; v0.y = o[nf][1] * li0;
        v1.x = o[nf][2] * li1; v1.y = o[nf][3] * li1;
        *(float2*)&Op[ri0 * DK_ + c] = v0;
        *(float2*)&Op[ri1 * DK_ + c] = v1;
    }
}

// ============================================================================
// Kernel 3: output projection (tf32 mma, cp.async pipelined).
// out = gather(g_ao) @ WO + bO
// ============================================================================
__global__ void __launch_bounds__(256, 2)
out_proj_mma(const float* __restrict__ WO,
             const float* __restrict__ bO,
             float* __restrict__ out)
{
    extern __shared__ float dsm[];
    const int row0 = blockIdx.y * 128;
    const int col0 = blockIdx.x * 128;
    const int tid  = threadIdx.x;
    const int lane = tid & 31;
    const int wid  = tid >> 5;
    const int wm   = (wid & 1) * 64;
    const int wn   = (wid >> 1) * 32;
    const int gr   = lane >> 2;
    const int tg   = lane & 3;

    const uint32_t sbase = (uint32_t)__cvta_generic_to_shared(dsm);

    int ar[4], ac[4], br[4], bc[4];
#pragma unroll
    for (int i = 0; i < 4; i++) {
        int f = tid + i * 256;
        ar[i] = f >> 3;  ac[i] = (f & 7) * 4;
        br[i] = f >> 5;  bc[i] = (f & 31) * 4;
    }

    auto issue = [&](int stage, int k0) {
        const uint32_t sa = sbase + (uint32_t)(stage * STG_FL) * 4u;
        const uint32_t sb = sa + (uint32_t)A_FL * 4u;
#pragma unroll
        for (int i = 0; i < 4; i++) {
            int row = row0 + ar[i];
            int b = row >> 11, s = row & (S_ - 1);
            int kg = k0 + ac[i];
            int h = kg >> 6, v = kg & 63;
            cpasync16(sa + (uint32_t)(ar[i] * AS_W + ac[i]) * 4u,
                      &g_ao[((b * H_ + h) * S_ + s) * DK_ + v]);
        }
#pragma unroll
        for (int i = 0; i < 4; i++)
            cpasync16(sb + (uint32_t)(br[i] * BS_W + bc[i]) * 4u,
                      WO + (k0 + br[i]) * D_ + col0 + bc[i]);
        cpcommit();
    };

    float acc[4][4][4];
#pragma unroll
    for (int i = 0; i < 4; i++)
#pragma unroll
        for (int j = 0; j < 4; j++)
#pragma unroll
            for (int r = 0; r < 4; r++) acc[i][j][r] = 0.0f;

    issue(0, 0);

    const int NK = D_ / 32;
    for (int kstep = 0; kstep < NK; kstep++) {
        const int stage = kstep & 1;
        float* Ab = dsm + stage * STG_FL;
        float* Bb = Ab + A_FL;

        cpwait0();
        __syncthreads();

        if (kstep + 1 < NK) issue(stage ^ 1, (kstep + 1) * 32);

#pragma unroll
        for (int i = 0; i < 4; i++) {
            float4* p = (float4*)(Ab + ar[i] * AS_W + ac[i]);
            float4 v = *p;
            v.x = tf(v.x); v.y = tf(v.y); v.z = tf(v.z); v.w = tf(v.w);
            *p = v;
        }
#pragma unroll
        for (int i = 0; i < 4; i++) {
            float4* p = (float4*)(Bb + br[i] * BS_W + bc[i]);
            float4 v = *p;
            v.x = tf(v.x); v.y = tf(v.y); v.z = tf(v.z); v.w = tf(v.w);
            *p = v;
        }
        __syncthreads();

#pragma unroll
        for (int ks = 0; ks < 4; ks++) {
            const int kk = ks * 8;
            uint32_t a[4][4], b[4][2];
#pragma unroll
            for (int mf = 0; mf < 4; mf++) {
                int m = wm + mf * 16;
                a[mf][0] = __float_as_uint(Ab[(m + gr) * AS_W + kk + tg]);
                a[mf][1] = __float_as_uint(Ab[(m + gr + 8) * AS_W + kk + tg]);
                a[mf][2] = __float_as_uint(Ab[(m + gr) * AS_W + kk + tg + 4]);
                a[mf][3] = __float_as_uint(Ab[(m + gr + 8) * AS_W + kk + tg + 4]);
            }
#pragma unroll
            for (int nf = 0; nf < 4; nf++) {
                int n = wn + nf * 8 + gr;
                b[nf][0] = __float_as_uint(Bb[(kk + tg) * BS_W + n]);
                b[nf][1] = __float_as_uint(Bb[(kk + tg + 4) * BS_W + n]);
            }
#pragma unroll
            for (int mf = 0; mf < 4; mf++)
#pragma unroll
                for (int nf = 0; nf < 4; nf++)
                    mma8(acc[mf][nf], a[mf], b[nf]);
        }
    }

#pragma unroll
    for (int mf = 0; mf < 4; mf++) {
#pragma unroll
        for (int rr = 0; rr < 2; rr++) {
            int r = row0 + wm + mf * 16 + gr + rr * 8;
#pragma unroll
            for (int nf = 0; nf < 4; nf++) {
                int c = col0 + wn + nf * 8 + 2 * tg;
                float2 v;
                v.x = acc[mf][nf][rr * 2 + 0] + bO[c];
                v.y = acc[mf][nf][rr * 2 + 1] + bO[c + 1];
                *(float2*)&out[r * D_ + c] = v;
            }
        }
    }
}

// ============================================================================
// launcher — inputs: 0 X, 1 mask(unused), 2 WQ, 3 WK, 4 WV, 5 WO, 6 bO
// ============================================================================
extern "C" void kernel_launch(void* const* d_in, const int* in_sizes, int n_in,
                              void* d_out, int out_size)
{
    (void)in_sizes; (void)n_in; (void)out_size;
    const float* X  = (const float*)d_in[0];
    const float* WQ = (const float*)d_in[2];
    const float* WK = (const float*)d_in[3];
    const float* WV = (const float*)d_in[4];
    const float* WO = (const float*)d_in[5];
    const float* bO = (const float*)d_in[6];
    float* out = (float*)d_out;

    static bool s_init = false;
    if (!s_init) {
        cudaFuncSetAttribute(proj_qkv_mma,
                             cudaFuncAttributeMaxDynamicSharedMemorySize,
                             PROJ_SMEM_BYTES);
        cudaFuncSetAttribute(attn_mma,
                             cudaFuncAttributeMaxDynamicSharedMemorySize,
                             ATTN_SMEM_BYTES);
        cudaFuncSetAttribute(out_proj_mma,
                             cudaFuncAttributeMaxDynamicSharedMemorySize,
                             PROJ_SMEM_BYTES);
        s_init = true;
    }

    {
        dim3 grid(D_ / 128, N_ / 128, 3);
        proj_qkv_mma<<<grid, 256, PROJ_SMEM_BYTES>>>(X, WQ, WK, WV);
    }
    {
        dim3 grid(BH_, S_ / 64);
        attn_mma<<<grid, 128, ATTN_SMEM_BYTES>>>();
    }
    {
        dim3 grid(D_ / 128, N_ / 128);
        out_proj_mma<<<grid, 256, PROJ_SMEM_BYTES>>>(WO, bO, out);
    }
}

// round 8
// speedup vs baseline: 1.1756x; 1.1756x over previous
#include <cuda_runtime.h>
#include <stdint.h>

#define B_  2
#define S_  2048
#define D_  1024
#define H_  16
#define DK_ 64
#define N_  (B_ * S_)            // 4096
#define BH_ (B_ * H_)            // 32

// ---------------- scratch (static device globals) ---------------------------
__device__ float g_x [N_ * D_];          // tf32-rounded input
__device__ float g_wq[D_ * D_];          // tf32-rounded weights
__device__ float g_wk[D_ * D_];
__device__ float g_wv[D_ * D_];
__device__ float g_wo[D_ * D_];
// layout [b][h][s][dk] — written ALREADY tf32-rounded by producer epilogues
__device__ float g_qp[BH_ * S_ * DK_];   // X @ WQ * scale   (key role)
__device__ float g_kp[BH_ * S_ * DK_];   // X @ WK           (query role)
__device__ float g_vp[BH_ * S_ * DK_];   // X @ WV
__device__ float g_ao[BH_ * S_ * DK_];   // attention output

// ---------------- tf32 helpers ----------------------------------------------
__device__ __forceinline__ uint32_t f2tf(float x) {
    uint32_t u; asm("cvt.rna.tf32.f32 %0, %1;" : "=r"(u) : "f"(x)); return u;
}
__device__ __forceinline__ float tf(float x) { return __uint_as_float(f2tf(x)); }

__device__ __forceinline__ void mma8(float* d, const uint32_t* a, const uint32_t* b) {
    asm volatile("mma.sync.aligned.m16n8k8.row.col.f32.tf32.tf32.f32 "
                 "{%0,%1,%2,%3}, {%4,%5,%6,%7}, {%8,%9}, {%0,%1,%2,%3};\n"
                 : "+f"(d[0]), "+f"(d[1]), "+f"(d[2]), "+f"(d[3])
                 : "r"(a[0]), "r"(a[1]), "r"(a[2]), "r"(a[3]),
                   "r"(b[0]), "r"(b[1]));
}

__device__ __forceinline__ void cpasync16(uint32_t smem_dst, const void* gptr) {
    asm volatile("cp.async.cg.shared.global [%0], [%1], 16;\n"
                 :: "r"(smem_dst), "l"(gptr));
}
__device__ __forceinline__ void cpcommit() {
    asm volatile("cp.async.commit_group;\n");
}
__device__ __forceinline__ void cpwait0() {
    asm volatile("cp.async.wait_group 0;\n");
}

// ============================================================================
// Kernel 0: tf32-RNA rounding prepass (pure bandwidth)
// ============================================================================
__global__ void tf32_round_copy(const float* __restrict__ src,
                                float* __restrict__ dst, int n4)
{
    int i = blockIdx.x * blockDim.x + threadIdx.x;
    int stride = gridDim.x * blockDim.x;
    const float4* s4 = (const float4*)src;
    float4* d4 = (float4*)dst;
    for (; i < n4; i += stride) {
        float4 v = s4[i];
        v.x = tf(v.x); v.y = tf(v.y); v.z = tf(v.z); v.w = tf(v.w);
        d4[i] = v;
    }
}

// ---------------- GEMM smem geometry -----------------------------------------
#define AS_W   36
#define BS_W   136
#define A_FL   (128 * AS_W)
#define B_FL   (32 * BS_W)
#define STG_FL (A_FL + B_FL)
#define PROJ_SMEM_BYTES (2 * STG_FL * 4)

// ============================================================================
// Kernel 1: QKV projection — pure cp.async double-buffered tf32 GEMM.
// Inputs pre-rounded; outputs rounded at epilogue (register cvt, free).
// ============================================================================
__global__ void __launch_bounds__(256, 2)
proj_qkv_mma()
{
    extern __shared__ float dsm[];
    const int mat = blockIdx.z;
    const float* __restrict__ W = (mat == 0) ? g_wq : (mat == 1) ? g_wk : g_wv;
    float* __restrict__ C = (mat == 0) ? g_qp : (mat == 1) ? g_kp : g_vp;
    const float alpha = (mat == 0) ? 0.125f : 1.0f;

    const int row0 = blockIdx.y * 128;
    const int col0 = blockIdx.x * 128;
    const int tid  = threadIdx.x;
    const int lane = tid & 31;
    const int wid  = tid >> 5;
    const int wm   = (wid & 1) * 64;
    const int wn   = (wid >> 1) * 32;
    const int gr   = lane >> 2;
    const int tg   = lane & 3;

    const uint32_t sbase = (uint32_t)__cvta_generic_to_shared(dsm);

    int ar[4], ac[4], br[4], bc[4];
#pragma unroll
    for (int i = 0; i < 4; i++) {
        int f = tid + i * 256;
        ar[i] = f >> 3;  ac[i] = (f & 7) * 4;
        br[i] = f >> 5;  bc[i] = (f & 31) * 4;
    }

    auto issue = [&](int stage, int k0) {
        const uint32_t sa = sbase + (uint32_t)(stage * STG_FL) * 4u;
        const uint32_t sb = sa + (uint32_t)A_FL * 4u;
#pragma unroll
        for (int i = 0; i < 4; i++)
            cpasync16(sa + (uint32_t)(ar[i] * AS_W + ac[i]) * 4u,
                      g_x + (row0 + ar[i]) * D_ + k0 + ac[i]);
#pragma unroll
        for (int i = 0; i < 4; i++)
            cpasync16(sb + (uint32_t)(br[i] * BS_W + bc[i]) * 4u,
                      W + (k0 + br[i]) * D_ + col0 + bc[i]);
        cpcommit();
    };

    float acc[4][4][4];
#pragma unroll
    for (int i = 0; i < 4; i++)
#pragma unroll
        for (int j = 0; j < 4; j++)
#pragma unroll
            for (int r = 0; r < 4; r++) acc[i][j][r] = 0.0f;

    issue(0, 0);

    const int NK = D_ / 32;
    for (int kstep = 0; kstep < NK; kstep++) {
        const int stage = kstep & 1;
        float* Ab = dsm + stage * STG_FL;
        float* Bb = Ab + A_FL;

        cpwait0();
        __syncthreads();
        if (kstep + 1 < NK) issue(stage ^ 1, (kstep + 1) * 32);

#pragma unroll
        for (int ks = 0; ks < 4; ks++) {
            const int kk = ks * 8;
            uint32_t a[4][4], b[4][2];
#pragma unroll
            for (int mf = 0; mf < 4; mf++) {
                int m = wm + mf * 16;
                a[mf][0] = __float_as_uint(Ab[(m + gr) * AS_W + kk + tg]);
                a[mf][1] = __float_as_uint(Ab[(m + gr + 8) * AS_W + kk + tg]);
                a[mf][2] = __float_as_uint(Ab[(m + gr) * AS_W + kk + tg + 4]);
                a[mf][3] = __float_as_uint(Ab[(m + gr + 8) * AS_W + kk + tg + 4]);
            }
#pragma unroll
            for (int nf = 0; nf < 4; nf++) {
                int n = wn + nf * 8 + gr;
                b[nf][0] = __float_as_uint(Bb[(kk + tg) * BS_W + n]);
                b[nf][1] = __float_as_uint(Bb[(kk + tg + 4) * BS_W + n]);
            }
#pragma unroll
            for (int mf = 0; mf < 4; mf++)
#pragma unroll
                for (int nf = 0; nf < 4; nf++)
                    mma8(acc[mf][nf], a[mf], b[nf]);
        }
    }

    // epilogue: scatter tf32-rounded into [b][h][s][dk]
#pragma unroll
    for (int mf = 0; mf < 4; mf++) {
#pragma unroll
        for (int rr = 0; rr < 2; rr++) {
            int r = row0 + wm + mf * 16 + gr + rr * 8;
            int b = r >> 11, s = r & (S_ - 1);
#pragma unroll
            for (int nf = 0; nf < 4; nf++) {
                int c = col0 + wn + nf * 8 + 2 * tg;
                int h = c >> 6, dk = c & 63;
                float2 v;
                v.x = tf(acc[mf][nf][rr * 2 + 0] * alpha);
                v.y = tf(acc[mf][nf][rr * 2 + 1] * alpha);
                *(float2*)&C[((b * H_ + h) * S_ + s) * DK_ + dk] = v;
            }
        }
    }
}

// ============================================================================
// Kernel 2: causal flash attention — register softmax, cp.async staged tiles,
// double-buffered K/V. Inputs pre-rounded; P rounded in regs; O rounded out.
// ============================================================================
#define MASKV   (-3.0e38f)
#define QW      68
#define VW      72
#define QFL     (64 * QW)
#define KFL     (64 * QW)
#define VFL     (64 * VW)
#define KV_FL   (KFL + VFL)
#define ATTN_SMEM_BYTES ((QFL + 2 * KV_FL) * 4)

__global__ void __launch_bounds__(128)
attn_mma()
{
    extern __shared__ float dsm[];
    float* Qs = dsm;                       // [64][QW]

    const int bh = blockIdx.x;
    const int qt = (gridDim.y - 1) - blockIdx.y;
    const float* __restrict__ Kp = g_qp + bh * S_ * DK_;  // key role (pre-scaled, pre-rounded)
    const float* __restrict__ Qp = g_kp + bh * S_ * DK_;  // query role (pre-rounded)
    const float* __restrict__ Vp = g_vp + bh * S_ * DK_;
    float* __restrict__ Op = g_ao + bh * S_ * DK_;

    const int t    = threadIdx.x;
    const int lane = t & 31;
    const int wid  = t >> 5;
    const int gr   = lane >> 2;
    const int tg   = lane & 3;
    const int wr   = wid * 16;

    const uint32_t sbase = (uint32_t)__cvta_generic_to_shared(dsm);

    // chunk map: f = t + i*128; r = f>>4 (0..63), c = (f&15)*4
    int cr[8], cc[8];
#pragma unroll
    for (int i = 0; i < 8; i++) {
        int f = t + i * 128;
        cr[i] = f >> 4;  cc[i] = (f & 15) * 4;
    }

    auto issue_kv = [&](int st, int kt) {
        const uint32_t sk = sbase + (uint32_t)(QFL + st * KV_FL) * 4u;
        const uint32_t sv = sk + (uint32_t)KFL * 4u;
#pragma unroll
        for (int i = 0; i < 8; i++)
            cpasync16(sk + (uint32_t)(cr[i] * QW + cc[i]) * 4u,
                      Kp + (kt * 64 + cr[i]) * DK_ + cc[i]);
#pragma unroll
        for (int i = 0; i < 8; i++)
            cpasync16(sv + (uint32_t)(cr[i] * VW + cc[i]) * 4u,
                      Vp + (kt * 64 + cr[i]) * DK_ + cc[i]);
        cpcommit();
    };

    // prologue: stage Q + KV(0) in one group
    {
#pragma unroll
        for (int i = 0; i < 8; i++)
            cpasync16(sbase + (uint32_t)(cr[i] * QW + cc[i]) * 4u,
                      Qp + (qt * 64 + cr[i]) * DK_ + cc[i]);
        issue_kv(0, 0);   // commits Q chunks together with KV0
    }
    cpwait0();
    __syncthreads();

    // preload Q a-fragments
    uint32_t qa[8][4];
#pragma unroll
    for (int ks = 0; ks < 8; ks++) {
        const int kk = ks * 8;
        qa[ks][0] = __float_as_uint(Qs[(wr + gr) * QW + kk + tg]);
        qa[ks][1] = __float_as_uint(Qs[(wr + gr + 8) * QW + kk + tg]);
        qa[ks][2] = __float_as_uint(Qs[(wr + gr) * QW + kk + tg + 4]);
        qa[ks][3] = __float_as_uint(Qs[(wr + gr + 8) * QW + kk + tg + 4]);
    }

    float o[8][4];
#pragma unroll
    for (int nf = 0; nf < 8; nf++)
#pragma unroll
        for (int r = 0; r < 4; r++) o[nf][r] = 0.0f;

    float m0 = MASKV, m1 = MASKV, l0 = 0.0f, l1 = 0.0f;
    const int ri0 = qt * 64 + wr + gr;
    const int ri1 = ri0 + 8;

    const int nkt = qt + 1;
    for (int kt = 0; kt < nkt; kt++) {
        const int st = kt & 1;
        float* Ks = dsm + QFL + st * KV_FL;
        float* Vs = Ks + KFL;

        cpwait0();          // KV(kt) arrived (no-op at kt=0)
        __syncthreads();    // all warps done with stage st (from kt-2) / see data
        if (kt + 1 < nkt) issue_kv(st ^ 1, kt + 1);

        // ---- S = Q @ K^T ----
        float sc[8][4];
#pragma unroll
        for (int nf = 0; nf < 8; nf++)
#pragma unroll
            for (int r = 0; r < 4; r++) sc[nf][r] = 0.0f;

#pragma unroll
        for (int ks = 0; ks < 8; ks++) {
            const int kk = ks * 8;
#pragma unroll
            for (int nf = 0; nf < 8; nf++) {
                uint32_t b[2];
                int n = nf * 8 + gr;
                b[0] = __float_as_uint(Ks[n * QW + kk + tg]);
                b[1] = __float_as_uint(Ks[n * QW + kk + tg + 4]);
                mma8(sc[nf], qa[ks], b);
            }
        }

        // ---- causal mask (diagonal tile) ----
        if (kt == qt) {
#pragma unroll
            for (int nf = 0; nf < 8; nf++) {
                int c0 = kt * 64 + nf * 8 + 2 * tg;
                if (c0 > ri0)     sc[nf][0] = MASKV;
                if (c0 + 1 > ri0) sc[nf][1] = MASKV;
                if (c0 > ri1)     sc[nf][2] = MASKV;
                if (c0 + 1 > ri1) sc[nf][3] = MASKV;
            }
        }

        // ---- register softmax ----
        float tm0 = MASKV, tm1 = MASKV;
#pragma unroll
        for (int nf = 0; nf < 8; nf++) {
            tm0 = fmaxf(tm0, fmaxf(sc[nf][0], sc[nf][1]));
            tm1 = fmaxf(tm1, fmaxf(sc[nf][2], sc[nf][3]));
        }
        tm0 = fmaxf(tm0, __shfl_xor_sync(0xffffffffu, tm0, 1));
        tm0 = fmaxf(tm0, __shfl_xor_sync(0xffffffffu, tm0, 2));
        tm1 = fmaxf(tm1, __shfl_xor_sync(0xffffffffu, tm1, 1));
        tm1 = fmaxf(tm1, __shfl_xor_sync(0xffffffffu, tm1, 2));

        float m0n = fmaxf(m0, tm0), m1n = fmaxf(m1, tm1);
        float corr0 = __expf(m0 - m0n), corr1 = __expf(m1 - m1n);
        float ps0 = 0.0f, ps1 = 0.0f;
#pragma unroll
        for (int nf = 0; nf < 8; nf++) {
            float e0 = __expf(sc[nf][0] - m0n);
            float e1 = __expf(sc[nf][1] - m0n);
            float e2 = __expf(sc[nf][2] - m1n);
            float e3 = __expf(sc[nf][3] - m1n);
            ps0 += e0 + e1; ps1 += e2 + e3;
            sc[nf][0] = tf(e0); sc[nf][1] = tf(e1);
            sc[nf][2] = tf(e2); sc[nf][3] = tf(e3);
        }
        ps0 += __shfl_xor_sync(0xffffffffu, ps0, 1);
        ps0 += __shfl_xor_sync(0xffffffffu, ps0, 2);
        ps1 += __shfl_xor_sync(0xffffffffu, ps1, 1);
        ps1 += __shfl_xor_sync(0xffffffffu, ps1, 2);
        l0 = l0 * corr0 + ps0;  l1 = l1 * corr1 + ps1;
        m0 = m0n;  m1 = m1n;

#pragma unroll
        for (int nf = 0; nf < 8; nf++) {
            o[nf][0] *= corr0; o[nf][1] *= corr0;
            o[nf][2] *= corr1; o[nf][3] *= corr1;
        }

        // ---- O += P @ V (quad-shfl C->A transform) ----
        const int src1 = (lane & ~3) | (tg >> 1);
        const int src2 = src1 + 2;
        const int sel  = tg & 1;
#pragma unroll
        for (int ks = 0; ks < 8; ks++) {
            float v00 = __shfl_sync(0xffffffffu, sc[ks][0], src1);
            float v01 = __shfl_sync(0xffffffffu, sc[ks][1], src1);
            float v10 = __shfl_sync(0xffffffffu, sc[ks][2], src1);
            float v11 = __shfl_sync(0xffffffffu, sc[ks][3], src1);
            float w00 = __shfl_sync(0xffffffffu, sc[ks][0], src2);
            float w01 = __shfl_sync(0xffffffffu, sc[ks][1], src2);
            float w10 = __shfl_sync(0xffffffffu, sc[ks][2], src2);
            float w11 = __shfl_sync(0xffffffffu, sc[ks][3], src2);
            uint32_t a[4];
            a[0] = __float_as_uint(sel ? v01 : v00);
            a[1] = __float_as_uint(sel ? v11 : v10);
            a[2] = __float_as_uint(sel ? w01 : w00);
            a[3] = __float_as_uint(sel ? w11 : w10);
            const int kk = ks * 8;
#pragma unroll
            for (int nf = 0; nf < 8; nf++) {
                uint32_t b[2];
                int n = nf * 8 + gr;
                b[0] = __float_as_uint(Vs[(kk + tg) * VW + n]);
                b[1] = __float_as_uint(Vs[(kk + tg + 4) * VW + n]);
                mma8(o[nf], a, b);
            }
        }
    }

    // epilogue: normalize, round, store (pre-rounded for out_proj)
    const float li0 = 1.0f / l0, li1 = 1.0f / l1;
#pragma unroll
    for (int nf = 0; nf < 8; nf++) {
        int c = nf * 8 + 2 * tg;
        float2 v0, v1;
        v0.x = tf(o[nf][0] * li0); v0.y = tf(o[nf][1] * li0);
        v1.x = tf(o[nf][2] * li1); v1.y = tf(o[nf][3] * li1);
        *(float2*)&Op[ri0 * DK_ + c] = v0;
        *(float2*)&Op[ri1 * DK_ + c] = v1;
    }
}

// ============================================================================
// Kernel 3: output projection — pure cp.async double-buffered tf32 GEMM.
// A (g_ao) and B (g_wo) are pre-rounded. Raw bias add at epilogue.
// ============================================================================
__global__ void __launch_bounds__(256, 2)
out_proj_mma(const float* __restrict__ bO, float* __restrict__ out)
{
    extern __shared__ float dsm[];
    const int row0 = blockIdx.y * 128;
    const int col0 = blockIdx.x * 128;
    const int tid  = threadIdx.x;
    const int lane = tid & 31;
    const int wid  = tid >> 5;
    const int wm   = (wid & 1) * 64;
    const int wn   = (wid >> 1) * 32;
    const int gr   = lane >> 2;
    const int tg   = lane & 3;

    const uint32_t sbase = (uint32_t)__cvta_generic_to_shared(dsm);

    int ar[4], ac[4], br[4], bc[4];
#pragma unroll
    for (int i = 0; i < 4; i++) {
        int f = tid + i * 256;
        ar[i] = f >> 3;  ac[i] = (f & 7) * 4;
        br[i] = f >> 5;  bc[i] = (f & 31) * 4;
    }

    auto issue = [&](int stage, int k0) {
        const uint32_t sa = sbase + (uint32_t)(stage * STG_FL) * 4u;
        const uint32_t sb = sa + (uint32_t)A_FL * 4u;
#pragma unroll
        for (int i = 0; i < 4; i++) {
            int row = row0 + ar[i];
            int b = row >> 11, s = row & (S_ - 1);
            int kg = k0 + ac[i];
            int h = kg >> 6, v = kg & 63;
            cpasync16(sa + (uint32_t)(ar[i] * AS_W + ac[i]) * 4u,
                      &g_ao[((b * H_ + h) * S_ + s) * DK_ + v]);
        }
#pragma unroll
        for (int i = 0; i < 4; i++)
            cpasync16(sb + (uint32_t)(br[i] * BS_W + bc[i]) * 4u,
                      g_wo + (k0 + br[i]) * D_ + col0 + bc[i]);
        cpcommit();
    };

    float acc[4][4][4];
#pragma unroll
    for (int i = 0; i < 4; i++)
#pragma unroll
        for (int j = 0; j < 4; j++)
#pragma unroll
            for (int r = 0; r < 4; r++) acc[i][j][r] = 0.0f;

    issue(0, 0);

    const int NK = D_ / 32;
    for (int kstep = 0; kstep < NK; kstep++) {
        const int stage = kstep & 1;
        float* Ab = dsm + stage * STG_FL;
        float* Bb = Ab + A_FL;

        cpwait0();
        __syncthreads();
        if (kstep + 1 < NK) issue(stage ^ 1, (kstep + 1) * 32);

#pragma unroll
        for (int ks = 0; ks < 4; ks++) {
            const int kk = ks * 8;
            uint32_t a[4][4], b[4][2];
#pragma unroll
            for (int mf = 0; mf < 4; mf++) {
                int m = wm + mf * 16;
                a[mf][0] = __float_as_uint(Ab[(m + gr) * AS_W + kk + tg]);
                a[mf][1] = __float_as_uint(Ab[(m + gr + 8) * AS_W + kk + tg]);
                a[mf][2] = __float_as_uint(Ab[(m + gr) * AS_W + kk + tg + 4]);
                a[mf][3] = __float_as_uint(Ab[(m + gr + 8) * AS_W + kk + tg + 4]);
            }
#pragma unroll
            for (int nf = 0; nf < 4; nf++) {
                int n = wn + nf * 8 + gr;
                b[nf][0] = __float_as_uint(Bb[(kk + tg) * BS_W + n]);
                b[nf][1] = __float_as_uint(Bb[(kk + tg + 4) * BS_W + n]);
            }
#pragma unroll
            for (int mf = 0; mf < 4; mf++)
#pragma unroll
                for (int nf = 0; nf < 4; nf++)
                    mma8(acc[mf][nf], a[mf], b[nf]);
        }
    }

#pragma unroll
    for (int mf = 0; mf < 4; mf++) {
#pragma unroll
        for (int rr = 0; rr < 2; rr++) {
            int r = row0 + wm + mf * 16 + gr + rr * 8;
#pragma unroll
            for (int nf = 0; nf < 4; nf++) {
                int c = col0 + wn + nf * 8 + 2 * tg;
                float2 v;
                v.x = acc[mf][nf][rr * 2 + 0] + bO[c];
                v.y = acc[mf][nf][rr * 2 + 1] + bO[c + 1];
                *(float2*)&out[r * D_ + c] = v;
            }
        }
    }
}

// ============================================================================
// launcher — inputs: 0 X, 1 mask(unused), 2 WQ, 3 WK, 4 WV, 5 WO, 6 bO
// ============================================================================
extern "C" void kernel_launch(void* const* d_in, const int* in_sizes, int n_in,
                              void* d_out, int out_size)
{
    (void)in_sizes; (void)n_in; (void)out_size;
    const float* X  = (const float*)d_in[0];
    const float* WQ = (const float*)d_in[2];
    const float* WK = (const float*)d_in[3];
    const float* WV = (const float*)d_in[4];
    const float* WO = (const float*)d_in[5];
    const float* bO = (const float*)d_in[6];
    float* out = (float*)d_out;

    static bool s_init = false;
    if (!s_init) {
        cudaFuncSetAttribute(proj_qkv_mma,
                             cudaFuncAttributeMaxDynamicSharedMemorySize,
                             PROJ_SMEM_BYTES);
        cudaFuncSetAttribute(attn_mma,
                             cudaFuncAttributeMaxDynamicSharedMemorySize,
                             ATTN_SMEM_BYTES);
        cudaFuncSetAttribute(out_proj_mma,
                             cudaFuncAttributeMaxDynamicSharedMemorySize,
                             PROJ_SMEM_BYTES);
        s_init = true;
    }

    // scratch pointers (host-side address resolution of __device__ globals is
    // not allowed inside capture-free zone? cudaGetSymbolAddress is fine — but
    // simplest: device code references the globals directly; prepass needs dst
    // pointers, so resolve once)
    static float *p_x = nullptr, *p_wq, *p_wk, *p_wv, *p_wo;
    if (!p_x) {
        cudaGetSymbolAddress((void**)&p_x,  g_x);
        cudaGetSymbolAddress((void**)&p_wq, g_wq);
        cudaGetSymbolAddress((void**)&p_wk, g_wk);
        cudaGetSymbolAddress((void**)&p_wv, g_wv);
        cudaGetSymbolAddress((void**)&p_wo, g_wo);
    }

    // prepass: round inputs/weights once per launch (X changes per call)
    tf32_round_copy<<<1024, 256>>>(X,  p_x,  (N_ * D_) / 4);
    tf32_round_copy<<<512, 256>>>(WQ, p_wq, (D_ * D_) / 4);
    tf32_round_copy<<<512, 256>>>(WK, p_wk, (D_ * D_) / 4);
    tf32_round_copy<<<512, 256>>>(WV, p_wv, (D_ * D_) / 4);
    tf32_round_copy<<<512, 256>>>(WO, p_wo, (D_ * D_) / 4);

    {
        dim3 grid(D_ / 128, N_ / 128, 3);
        proj_qkv_mma<<<grid, 256, PROJ_SMEM_BYTES>>>();
    }
    {
        dim3 grid(BH_, S_ / 64);
        attn_mma<<<grid, 128, ATTN_SMEM_BYTES>>>();
    }
    {
        dim3 grid(D_ / 128, N_ / 128);
        out_proj_mma<<<grid, 256, PROJ_SMEM_BYTES>>>(bO, out);
    }
}

// round 10
// speedup vs baseline: 1.1889x; 1.0113x over previous
#include <cuda_runtime.h>
#include <stdint.h>

#define B_  2
#define S_  2048
#define D_  1024
#define H_  16
#define DK_ 64
#define N_  (B_ * S_)            // 4096
#define BH_ (B_ * H_)            // 32

// ---------------- scratch (static device globals) ---------------------------
__device__ float g_x [N_ * D_];          // tf32-rounded input
__device__ float g_wq[D_ * D_];          // tf32-rounded weights
__device__ float g_wk[D_ * D_];
__device__ float g_wv[D_ * D_];
__device__ float g_wo[D_ * D_];
// layout [b][h][s][dk] — written ALREADY tf32-rounded by producer epilogues
__device__ float g_qp[BH_ * S_ * DK_];   // X @ WQ * scale   (key role)
__device__ float g_kp[BH_ * S_ * DK_];   // X @ WK           (query role)
__device__ float g_vp[BH_ * S_ * DK_];   // X @ WV
__device__ float g_ao[BH_ * S_ * DK_];   // attention output

// ---------------- tf32 helpers ----------------------------------------------
__device__ __forceinline__ uint32_t f2tf(float x) {
    uint32_t u; asm("cvt.rna.tf32.f32 %0, %1;" : "=r"(u) : "f"(x)); return u;
}
__device__ __forceinline__ float tf(float x) { return __uint_as_float(f2tf(x)); }

__device__ __forceinline__ void mma8(float* d, const uint32_t* a, const uint32_t* b) {
    asm volatile("mma.sync.aligned.m16n8k8.row.col.f32.tf32.tf32.f32 "
                 "{%0,%1,%2,%3}, {%4,%5,%6,%7}, {%8,%9}, {%0,%1,%2,%3};\n"
                 : "+f"(d[0]), "+f"(d[1]), "+f"(d[2]), "+f"(d[3])
                 : "r"(a[0]), "r"(a[1]), "r"(a[2]), "r"(a[3]),
                   "r"(b[0]), "r"(b[1]));
}

__device__ __forceinline__ void cpasync16(uint32_t smem_dst, const void* gptr) {
    asm volatile("cp.async.cg.shared.global [%0], [%1], 16;\n"
                 :: "r"(smem_dst), "l"(gptr));
}
__device__ __forceinline__ void cpcommit() {
    asm volatile("cp.async.commit_group;\n");
}
__device__ __forceinline__ void cpwait0() {
    asm volatile("cp.async.wait_group 0;\n");
}

// ============================================================================
// Kernel 0: fused tf32-RNA rounding prepass (X + 4 weights, one launch)
// ============================================================================
#define XF4   ((N_ * D_) / 4)            // 1M float4
#define WF4   ((D_ * D_) / 4)            // 256K float4
#define TOTF4 (XF4 + 4 * WF4)            // 2M float4

__global__ void tf32_round_all(const float* __restrict__ X,
                               const float* __restrict__ WQ,
                               const float* __restrict__ WK,
                               const float* __restrict__ WV,
                               const float* __restrict__ WO)
{
    int i = blockIdx.x * blockDim.x + threadIdx.x;
    int stride = gridDim.x * blockDim.x;
    for (; i < TOTF4; i += stride) {
        const float4* s4; float4* d4; int off;
        if (i < XF4)              { s4 = (const float4*)X;  d4 = (float4*)g_x;  off = i; }
        else if (i < XF4 + WF4)   { s4 = (const float4*)WQ; d4 = (float4*)g_wq; off = i - XF4; }
        else if (i < XF4 + 2*WF4) { s4 = (const float4*)WK; d4 = (float4*)g_wk; off = i - XF4 - WF4; }
        else if (i < XF4 + 3*WF4) { s4 = (const float4*)WV; d4 = (float4*)g_wv; off = i - XF4 - 2*WF4; }
        else                      { s4 = (const float4*)WO; d4 = (float4*)g_wo; off = i - XF4 - 3*WF4; }
        float4 v = s4[off];
        v.x = tf(v.x); v.y = tf(v.y); v.z = tf(v.z); v.w = tf(v.w);
        d4[off] = v;
    }
}

// ---------------- GEMM smem geometry -----------------------------------------
#define AS_W   36
#define BS_W   136
#define A_FL   (128 * AS_W)
#define B_FL   (32 * BS_W)
#define STG_FL (A_FL + B_FL)
#define PROJ_SMEM_BYTES (2 * STG_FL * 4)

// ============================================================================
// Kernel 1: QKV projection — pure cp.async double-buffered tf32 GEMM.
// ============================================================================
__global__ void __launch_bounds__(256, 2)
proj_qkv_mma()
{
    extern __shared__ float dsm[];
    const int mat = blockIdx.z;
    const float* __restrict__ W = (mat == 0) ? g_wq : (mat == 1) ? g_wk : g_wv;
    float* __restrict__ C = (mat == 0) ? g_qp : (mat == 1) ? g_kp : g_vp;
    const float alpha = (mat == 0) ? 0.125f : 1.0f;

    const int row0 = blockIdx.y * 128;
    const int col0 = blockIdx.x * 128;
    const int tid  = threadIdx.x;
    const int lane = tid & 31;
    const int wid  = tid >> 5;
    const int wm   = (wid & 1) * 64;
    const int wn   = (wid >> 1) * 32;
    const int gr   = lane >> 2;
    const int tg   = lane & 3;

    const uint32_t sbase = (uint32_t)__cvta_generic_to_shared(dsm);

    int ar[4], ac[4], br[4], bc[4];
#pragma unroll
    for (int i = 0; i < 4; i++) {
        int f = tid + i * 256;
        ar[i] = f >> 3;  ac[i] = (f & 7) * 4;
        br[i] = f >> 5;  bc[i] = (f & 31) * 4;
    }

    auto issue = [&](int stage, int k0) {
        const uint32_t sa = sbase + (uint32_t)(stage * STG_FL) * 4u;
        const uint32_t sb = sa + (uint32_t)A_FL * 4u;
#pragma unroll
        for (int i = 0; i < 4; i++)
            cpasync16(sa + (uint32_t)(ar[i] * AS_W + ac[i]) * 4u,
                      g_x + (row0 + ar[i]) * D_ + k0 + ac[i]);
#pragma unroll
        for (int i = 0; i < 4; i++)
            cpasync16(sb + (uint32_t)(br[i] * BS_W + bc[i]) * 4u,
                      W + (k0 + br[i]) * D_ + col0 + bc[i]);
        cpcommit();
    };

    float acc[4][4][4];
#pragma unroll
    for (int i = 0; i < 4; i++)
#pragma unroll
        for (int j = 0; j < 4; j++)
#pragma unroll
            for (int r = 0; r < 4; r++) acc[i][j][r] = 0.0f;

    issue(0, 0);

    const int NK = D_ / 32;
    for (int kstep = 0; kstep < NK; kstep++) {
        const int stage = kstep & 1;
        float* Ab = dsm + stage * STG_FL;
        float* Bb = Ab + A_FL;

        cpwait0();
        __syncthreads();
        if (kstep + 1 < NK) issue(stage ^ 1, (kstep + 1) * 32);

#pragma unroll
        for (int ks = 0; ks < 4; ks++) {
            const int kk = ks * 8;
            uint32_t a[4][4], b[4][2];
#pragma unroll
            for (int mf = 0; mf < 4; mf++) {
                int m = wm + mf * 16;
                a[mf][0] = __float_as_uint(Ab[(m + gr) * AS_W + kk + tg]);
                a[mf][1] = __float_as_uint(Ab[(m + gr + 8) * AS_W + kk + tg]);
                a[mf][2] = __float_as_uint(Ab[(m + gr) * AS_W + kk + tg + 4]);
                a[mf][3] = __float_as_uint(Ab[(m + gr + 8) * AS_W + kk + tg + 4]);
            }
#pragma unroll
            for (int nf = 0; nf < 4; nf++) {
                int n = wn + nf * 8 + gr;
                b[nf][0] = __float_as_uint(Bb[(kk + tg) * BS_W + n]);
                b[nf][1] = __float_as_uint(Bb[(kk + tg + 4) * BS_W + n]);
            }
#pragma unroll
            for (int mf = 0; mf < 4; mf++)
#pragma unroll
                for (int nf = 0; nf < 4; nf++)
                    mma8(acc[mf][nf], a[mf], b[nf]);
        }
    }

#pragma unroll
    for (int mf = 0; mf < 4; mf++) {
#pragma unroll
        for (int rr = 0; rr < 2; rr++) {
            int r = row0 + wm + mf * 16 + gr + rr * 8;
            int b = r >> 11, s = r & (S_ - 1);
#pragma unroll
            for (int nf = 0; nf < 4; nf++) {
                int c = col0 + wn + nf * 8 + 2 * tg;
                int h = c >> 6, dk = c & 63;
                float2 v;
                v.x = tf(acc[mf][nf][rr * 2 + 0] * alpha);
                v.y = tf(acc[mf][nf][rr * 2 + 1] * alpha);
                *(float2*)&C[((b * H_ + h) * S_ + s) * DK_ + dk] = v;
            }
        }
    }
}

// ============================================================================
// Kernel 2: causal flash attention — BQ=128 (8 warps over M), register softmax,
// cp.async double-buffered K/V. All inputs pre-rounded.
// ============================================================================
#define MASKV   (-3.0e38f)
#define QW      68
#define VW      72
#define QFL     (128 * QW)
#define KFL     (64 * QW)
#define VFL     (64 * VW)
#define KV_FL   (KFL + VFL)
#define ATTN_SMEM_BYTES ((QFL + 2 * KV_FL) * 4)

__global__ void __launch_bounds__(256)
attn_mma()
{
    extern __shared__ float dsm[];
    float* Qs = dsm;                       // [128][QW]

    const int bh = blockIdx.x;
    const int qt = (gridDim.y - 1) - blockIdx.y;   // heavy tiles first
    const float* __restrict__ Kp = g_qp + bh * S_ * DK_;  // key role (pre-scaled)
    const float* __restrict__ Qp = g_kp + bh * S_ * DK_;  // query role
    const float* __restrict__ Vp = g_vp + bh * S_ * DK_;
    float* __restrict__ Op = g_ao + bh * S_ * DK_;

    const int t    = threadIdx.x;
    const int lane = t & 31;
    const int wid  = t >> 5;          // 0..7
    const int gr   = lane >> 2;
    const int tg   = lane & 3;
    const int wr   = wid * 16;        // warp's query-row base (0..112)

    const uint32_t sbase = (uint32_t)__cvta_generic_to_shared(dsm);

    // KV chunk map: f = t + i*256 (i<4); r = f>>4 (0..63), c = (f&15)*4
    int cr[4], cc[4];
#pragma unroll
    for (int i = 0; i < 4; i++) {
        int f = t + i * 256;
        cr[i] = f >> 4;  cc[i] = (f & 15) * 4;
    }

    auto issue_kv = [&](int st, int kt) {
        const uint32_t sk = sbase + (uint32_t)(QFL + st * KV_FL) * 4u;
        const uint32_t sv = sk + (uint32_t)KFL * 4u;
#pragma unroll
        for (int i = 0; i < 4; i++)
            cpasync16(sk + (uint32_t)(cr[i] * QW + cc[i]) * 4u,
                      Kp + (kt * 64 + cr[i]) * DK_ + cc[i]);
#pragma unroll
        for (int i = 0; i < 4; i++)
            cpasync16(sv + (uint32_t)(cr[i] * VW + cc[i]) * 4u,
                      Vp + (kt * 64 + cr[i]) * DK_ + cc[i]);
        cpcommit();
    };

    // prologue: stage Q (128x64) + KV(0) in one group
    {
#pragma unroll
        for (int i = 0; i < 8; i++) {
            int f = t + i * 256;
            int r = f >> 4, c = (f & 15) * 4;
            cpasync16(sbase + (uint32_t)(r * QW + c) * 4u,
                      Qp + (qt * 128 + r) * DK_ + c);
        }
        issue_kv(0, 0);
    }
    cpwait0();
    __syncthreads();

    // preload Q a-fragments
    uint32_t qa[8][4];
#pragma unroll
    for (int ks = 0; ks < 8; ks++) {
        const int kk = ks * 8;
        qa[ks][0] = __float_as_uint(Qs[(wr + gr) * QW + kk + tg]);
        qa[ks][1] = __float_as_uint(Qs[(wr + gr + 8) * QW + kk + tg]);
        qa[ks][2] = __float_as_uint(Qs[(wr + gr) * QW + kk + tg + 4]);
        qa[ks][3] = __float_as_uint(Qs[(wr + gr + 8) * QW + kk + tg + 4]);
    }

    float o[8][4];
#pragma unroll
    for (int nf = 0; nf < 8; nf++)
#pragma unroll
        for (int r = 0; r < 4; r++) o[nf][r] = 0.0f;

    float m0 = MASKV, m1 = MASKV, l0 = 0.0f, l1 = 0.0f;
    const int ri0 = qt * 128 + wr + gr;
    const int ri1 = ri0 + 8;

    const int nkt = 2 * qt + 2;
    for (int kt = 0; kt < nkt; kt++) {
        const int st = kt & 1;
        float* Ks = dsm + QFL + st * KV_FL;
        float* Vs = Ks + KFL;

        cpwait0();
        __syncthreads();
        if (kt + 1 < nkt) issue_kv(st ^ 1, kt + 1);

        // ---- S = Q @ K^T ----
        float sc[8][4];
#pragma unroll
        for (int nf = 0; nf < 8; nf++)
#pragma unroll
            for (int r = 0; r < 4; r++) sc[nf][r] = 0.0f;

#pragma unroll
        for (int ks = 0; ks < 8; ks++) {
            const int kk = ks * 8;
#pragma unroll
            for (int nf = 0; nf < 8; nf++) {
                uint32_t b[2];
                int n = nf * 8 + gr;
                b[0] = __float_as_uint(Ks[n * QW + kk + tg]);
                b[1] = __float_as_uint(Ks[n * QW + kk + tg + 4]);
                mma8(sc[nf], qa[ks], b);
            }
        }

        // ---- causal mask (last two k-tiles straddle the diagonal) ----
        if (kt >= nkt - 2) {
#pragma unroll
            for (int nf = 0; nf < 8; nf++) {
                int c0 = kt * 64 + nf * 8 + 2 * tg;
                if (c0 > ri0)     sc[nf][0] = MASKV;
                if (c0 + 1 > ri0) sc[nf][1] = MASKV;
                if (c0 > ri1)     sc[nf][2] = MASKV;
                if (c0 + 1 > ri1) sc[nf][3] = MASKV;
            }
        }

        // ---- register softmax ----
        float tm0 = MASKV, tm1 = MASKV;
#pragma unroll
        for (int nf = 0; nf < 8; nf++) {
            tm0 = fmaxf(tm0, fmaxf(sc[nf][0], sc[nf][1]));
            tm1 = fmaxf(tm1, fmaxf(sc[nf][2], sc[nf][3]));
        }
        tm0 = fmaxf(tm0, __shfl_xor_sync(0xffffffffu, tm0, 1));
        tm0 = fmaxf(tm0, __shfl_xor_sync(0xffffffffu, tm0, 2));
        tm1 = fmaxf(tm1, __shfl_xor_sync(0xffffffffu, tm1, 1));
        tm1 = fmaxf(tm1, __shfl_xor_sync(0xffffffffu, tm1, 2));

        float m0n = fmaxf(m0, tm0), m1n = fmaxf(m1, tm1);
        float corr0 = __expf(m0 - m0n), corr1 = __expf(m1 - m1n);
        float ps0 = 0.0f, ps1 = 0.0f;
#pragma unroll
        for (int nf = 0; nf < 8; nf++) {
            float e0 = __expf(sc[nf][0] - m0n);
            float e1 = __expf(sc[nf][1] - m0n);
            float e2 = __expf(sc[nf][2] - m1n);
            float e3 = __expf(sc[nf][3] - m1n);
            ps0 += e0 + e1; ps1 += e2 + e3;
            sc[nf][0] = tf(e0); sc[nf][1] = tf(e1);
            sc[nf][2] = tf(e2); sc[nf][3] = tf(e3);
        }
        ps0 += __shfl_xor_sync(0xffffffffu, ps0, 1);
        ps0 += __shfl_xor_sync(0xffffffffu, ps0, 2);
        ps1 += __shfl_xor_sync(0xffffffffu, ps1, 1);
        ps1 += __shfl_xor_sync(0xffffffffu, ps1, 2);
        l0 = l0 * corr0 + ps0;  l1 = l1 * corr1 + ps1;
        m0 = m0n;  m1 = m1n;

#pragma unroll
        for (int nf = 0; nf < 8; nf++) {
            o[nf][0] *= corr0; o[nf][1] *= corr0;
            o[nf][2] *= corr1; o[nf][3] *= corr1;
        }

        // ---- O += P @ V (quad-shfl C->A transform) ----
        const int src1 = (lane & ~3) | (tg >> 1);
        const int src2 = src1 + 2;
        const int sel  = tg & 1;
#pragma unroll
        for (int ks = 0; ks < 8; ks++) {
            float v00 = __shfl_sync(0xffffffffu, sc[ks][0], src1);
            float v01 = __shfl_sync(0xffffffffu, sc[ks][1], src1);
            float v10 = __shfl_sync(0xffffffffu, sc[ks][2], src1);
            float v11 = __shfl_sync(0xffffffffu, sc[ks][3], src1);
            float w00 = __shfl_sync(0xffffffffu, sc[ks][0], src2);
            float w01 = __shfl_sync(0xffffffffu, sc[ks][1], src2);
            float w10 = __shfl_sync(0xffffffffu, sc[ks][2], src2);
            float w11 = __shfl_sync(0xffffffffu, sc[ks][3], src2);
            uint32_t a[4];
            a[0] = __float_as_uint(sel ? v01 : v00);
            a[1] = __float_as_uint(sel ? v11 : v10);
            a[2] = __float_as_uint(sel ? w01 : w00);
            a[3] = __float_as_uint(sel ? w11 : w10);
            const int kk = ks * 8;
#pragma unroll
            for (int nf = 0; nf < 8; nf++) {
                uint32_t b[2];
                int n = nf * 8 + gr;
                b[0] = __float_as_uint(Vs[(kk + tg) * VW + n]);
                b[1] = __float_as_uint(Vs[(kk + tg + 4) * VW + n]);
                mma8(o[nf], a, b);
            }
        }
    }

    // epilogue: normalize, round, store
    const float li0 = 1.0f / l0, li1 = 1.0f / l1;
#pragma unroll
    for (int nf = 0; nf < 8; nf++) {
        int c = nf * 8 + 2 * tg;
        float2 v0, v1;
        v0.x = tf(o[nf][0] * li0); v0.y = tf(o[nf][1] * li0);
        v1.x = tf(o[nf][2] * li1); v1.y = tf(o[nf][3] * li1);
        *(float2*)&Op[ri0 * DK_ + c] = v0;
        *(float2*)&Op[ri1 * DK_ + c] = v1;
    }
}

// ============================================================================
// Kernel 3: output projection — pure cp.async double-buffered tf32 GEMM.
// ============================================================================
__global__ void __launch_bounds__(256, 2)
out_proj_mma(const float* __restrict__ bO, float* __restrict__ out)
{
    extern __shared__ float dsm[];
    const int row0 = blockIdx.y * 128;
    const int col0 = blockIdx.x * 128;
    const int tid  = threadIdx.x;
    const int lane = tid & 31;
    const int wid  = tid >> 5;
    const int wm   = (wid & 1) * 64;
    const int wn   = (wid >> 1) * 32;
    const int gr   = lane >> 2;
    const int tg   = lane & 3;

    const uint32_t sbase = (uint32_t)__cvta_generic_to_shared(dsm);

    int ar[4], ac[4], br[4], bc[4];
#pragma unroll
    for (int i = 0; i < 4; i++) {
        int f = tid + i * 256;
        ar[i] = f >> 3;  ac[i] = (f & 7) * 4;
        br[i] = f >> 5;  bc[i] = (f & 31) * 4;
    }

    auto issue = [&](int stage, int k0) {
        const uint32_t sa = sbase + (uint32_t)(stage * STG_FL) * 4u;
        const uint32_t sb = sa + (uint32_t)A_FL * 4u;
#pragma unroll
        for (int i = 0; i < 4; i++) {
            int row = row0 + ar[i];
            int b = row >> 11, s = row & (S_ - 1);
            int kg = k0 + ac[i];
            int h = kg >> 6, v = kg & 63;
            cpasync16(sa + (uint32_t)(ar[i] * AS_W + ac[i]) * 4u,
                      &g_ao[((b * H_ + h) * S_ + s) * DK_ + v]);
        }
#pragma unroll
        for (int i = 0; i < 4; i++)
            cpasync16(sb + (uint32_t)(br[i] * BS_W + bc[i]) * 4u,
                      g_wo + (k0 + br[i]) * D_ + col0 + bc[i]);
        cpcommit();
    };

    float acc[4][4][4];
#pragma unroll
    for (int i = 0; i < 4; i++)
#pragma unroll
        for (int j = 0; j < 4; j++)
#pragma unroll
            for (int r = 0; r < 4; r++) acc[i][j][r] = 0.0f;

    issue(0, 0);

    const int NK = D_ / 32;
    for (int kstep = 0; kstep < NK; kstep++) {
        const int stage = kstep & 1;
        float* Ab = dsm + stage * STG_FL;
        float* Bb = Ab + A_FL;

        cpwait0();
        __syncthreads();
        if (kstep + 1 < NK) issue(stage ^ 1, (kstep + 1) * 32);

#pragma unroll
        for (int ks = 0; ks < 4; ks++) {
            const int kk = ks * 8;
            uint32_t a[4][4], b[4][2];
#pragma unroll
            for (int mf = 0; mf < 4; mf++) {
                int m = wm + mf * 16;
                a[mf][0] = __float_as_uint(Ab[(m + gr) * AS_W + kk + tg]);
                a[mf][1] = __float_as_uint(Ab[(m + gr + 8) * AS_W + kk + tg]);
                a[mf][2] = __float_as_uint(Ab[(m + gr) * AS_W + kk + tg + 4]);
                a[mf][3] = __float_as_uint(Ab[(m + gr + 8) * AS_W + kk + tg + 4]);
            }
#pragma unroll
            for (int nf = 0; nf < 4; nf++) {
                int n = wn + nf * 8 + gr;
                b[nf][0] = __float_as_uint(Bb[(kk + tg) * BS_W + n]);
                b[nf][1] = __float_as_uint(Bb[(kk + tg + 4) * BS_W + n]);
            }
#pragma unroll
            for (int mf = 0; mf < 4; mf++)
#pragma unroll
                for (int nf = 0; nf < 4; nf++)
                    mma8(acc[mf][nf], a[mf], b[nf]);
        }
    }

#pragma unroll
    for (int mf = 0; mf < 4; mf++) {
#pragma unroll
        for (int rr = 0; rr < 2; rr++) {
            int r = row0 + wm + mf * 16 + gr + rr * 8;
#pragma unroll
            for (int nf = 0; nf < 4; nf++) {
                int c = col0 + wn + nf * 8 + 2 * tg;
                float2 v;
                v.x = acc[mf][nf][rr * 2 + 0] + bO[c];
                v.y = acc[mf][nf][rr * 2 + 1] + bO[c + 1];
                *(float2*)&out[r * D_ + c] = v;
            }
        }
    }
}

// ============================================================================
// launcher — inputs: 0 X, 1 mask(unused), 2 WQ, 3 WK, 4 WV, 5 WO, 6 bO
// ============================================================================
extern "C" void kernel_launch(void* const* d_in, const int* in_sizes, int n_in,
                              void* d_out, int out_size)
{
    (void)in_sizes; (void)n_in; (void)out_size;
    const float* X  = (const float*)d_in[0];
    const float* WQ = (const float*)d_in[2];
    const float* WK = (const float*)d_in[3];
    const float* WV = (const float*)d_in[4];
    const float* WO = (const float*)d_in[5];
    const float* bO = (const float*)d_in[6];
    float* out = (float*)d_out;

    static bool s_init = false;
    if (!s_init) {
        cudaFuncSetAttribute(proj_qkv_mma,
                             cudaFuncAttributeMaxDynamicSharedMemorySize,
                             PROJ_SMEM_BYTES);
        cudaFuncSetAttribute(attn_mma,
                             cudaFuncAttributeMaxDynamicSharedMemorySize,
                             ATTN_SMEM_BYTES);
        cudaFuncSetAttribute(out_proj_mma,
                             cudaFuncAttributeMaxDynamicSharedMemorySize,
                             PROJ_SMEM_BYTES);
        s_init = true;
    }

    tf32_round_all<<<2048, 256>>>(X, WQ, WK, WV, WO);

    {
        dim3 grid(D_ / 128, N_ / 128, 3);
        proj_qkv_mma<<<grid, 256, PROJ_SMEM_BYTES>>>();
    }
    {
        dim3 grid(BH_, S_ / 128);
        attn_mma<<<grid, 256, ATTN_SMEM_BYTES>>>();
    }
    {
        dim3 grid(D_ / 128, N_ / 128);
        out_proj_mma<<<grid, 256, PROJ_SMEM_BYTES>>>(bO, out);
    }
}

// round 12
// speedup vs baseline: 1.2281x; 1.0330x over previous
#include <cuda_runtime.h>
#include <stdint.h>

#define B_  2
#define S_  2048
#define D_  1024
#define H_  16
#define DK_ 64
#define N_  (B_ * S_)            // 4096
#define BH_ (B_ * H_)            // 32

// ---------------- scratch (static device globals) ---------------------------
__device__ float g_x [N_ * D_];          // tf32-rounded input (row-major [m][k])
__device__ float g_wq[D_ * D_];          // tf32-rounded TRANSPOSED weights [n][k]
__device__ float g_wk[D_ * D_];
__device__ float g_wv[D_ * D_];
__device__ float g_wo[D_ * D_];
// layout [b][h][s][dk] — written ALREADY tf32-rounded by producer epilogues
__device__ float g_qp[BH_ * S_ * DK_];   // X @ WQ * scale   (key role)
__device__ float g_kp[BH_ * S_ * DK_];   // X @ WK           (query role)
__device__ float g_vp[BH_ * S_ * DK_];   // X @ WV
__device__ float g_ao[BH_ * S_ * DK_];   // attention output

// ---------------- helpers ----------------------------------------------------
__device__ __forceinline__ uint32_t f2tf(float x) {
    uint32_t u; asm("cvt.rna.tf32.f32 %0, %1;" : "=r"(u) : "f"(x)); return u;
}
__device__ __forceinline__ float tf(float x) { return __uint_as_float(f2tf(x)); }

__device__ __forceinline__ void mma8(float* d, const uint32_t* a, const uint32_t* b) {
    asm volatile("mma.sync.aligned.m16n8k8.row.col.f32.tf32.tf32.f32 "
                 "{%0,%1,%2,%3}, {%4,%5,%6,%7}, {%8,%9}, {%0,%1,%2,%3};\n"
                 : "+f"(d[0]), "+f"(d[1]), "+f"(d[2]), "+f"(d[3])
                 : "r"(a[0]), "r"(a[1]), "r"(a[2]), "r"(a[3]),
                   "r"(b[0]), "r"(b[1]));
}

__device__ __forceinline__ void ldsm4(uint32_t* r, uint32_t addr) {
    asm volatile("ldmatrix.sync.aligned.m8n8.x4.shared.b16 {%0,%1,%2,%3}, [%4];"
                 : "=r"(r[0]), "=r"(r[1]), "=r"(r[2]), "=r"(r[3]) : "r"(addr));
}

__device__ __forceinline__ void cpasync16(uint32_t smem_dst, const void* gptr) {
    asm volatile("cp.async.cg.shared.global [%0], [%1], 16;\n"
                 :: "r"(smem_dst), "l"(gptr));
}
__device__ __forceinline__ void cpcommit() {
    asm volatile("cp.async.commit_group;\n");
}
__device__ __forceinline__ void cpwait0() {
    asm volatile("cp.async.wait_group 0;\n");
}
__device__ __forceinline__ void cpwait1() {
    asm volatile("cp.async.wait_group 1;\n");
}

// ============================================================================
// Kernel 0a: X rounding (grid-stride)
// ============================================================================
#define XF4 ((N_ * D_) / 4)
__global__ void x_round(const float* __restrict__ X)
{
    int i = blockIdx.x * blockDim.x + threadIdx.x;
    int stride = gridDim.x * blockDim.x;
    const float4* s4 = (const float4*)X;
    float4* d4 = (float4*)g_x;
    for (; i < XF4; i += stride) {
        float4 v = s4[i];
        v.x = tf(v.x); v.y = tf(v.y); v.z = tf(v.z); v.w = tf(v.w);
        d4[i] = v;
    }
}

// ============================================================================
// Kernel 0b: weight transpose + round: dst[n][k] = tf(src[k][n])
// ============================================================================
__global__ void w_trans(const float* __restrict__ WQ, const float* __restrict__ WK,
                        const float* __restrict__ WV, const float* __restrict__ WO)
{
    const int mat = blockIdx.z;
    const float* __restrict__ src = (mat == 0) ? WQ : (mat == 1) ? WK : (mat == 2) ? WV : WO;
    float* __restrict__ dst = (mat == 0) ? g_wq : (mat == 1) ? g_wk : (mat == 2) ? g_wv : g_wo;

    __shared__ float tile[32][33];
    const int n0 = blockIdx.x * 32, k0 = blockIdx.y * 32;
    const int tx = threadIdx.x, ty = threadIdx.y;
#pragma unroll
    for (int i = 0; i < 4; i++)
        tile[ty + i * 8][tx] = tf(src[(k0 + ty + i * 8) * D_ + n0 + tx]);
    __syncthreads();
#pragma unroll
    for (int i = 0; i < 4; i++)
        dst[(n0 + ty + i * 8) * D_ + k0 + tx] = tile[tx][ty + i * 8];
}

// ---------------- GEMM geometry ----------------------------------------------
// Both A and B staged as 128 rows x 32 k-floats, row stride 144B (36 floats):
// 16B-aligned rows, LDSM-conflict-free (16*i mod 128 distinct over 8 rows).
#define TROW_B   144                        // bytes per staged row
#define TILE_FL  (128 * 36)                 // floats per tile
#define TILE_BB  (TILE_FL * 4)              // 18432 B
#define STG_BB   (2 * TILE_BB)              // A+B per stage
#define GS_SMEM  (3 * STG_BB)               // 110592 B
#define NKT      32                         // 1024 / 32

// ============================================================================
// Kernel 1: QKV projection — ldmatrix + mma.sync, 3-stage ring, 1 sync/ktile.
// 256 thr, 8 warps (2M x 4N), warp tile 64x32. grid (8, 32, 3).
// ============================================================================
__global__ void __launch_bounds__(256, 2)
proj_qkv_mma()
{
    extern __shared__ float dsm[];
    const uint32_t sbase = (uint32_t)__cvta_generic_to_shared(dsm);
    const int mat = blockIdx.z;
    const float* __restrict__ W = (mat == 0) ? g_wq : (mat == 1) ? g_wk : g_wv;
    float* __restrict__ C = (mat == 0) ? g_qp : (mat == 1) ? g_kp : g_vp;
    const float alpha = (mat == 0) ? 0.125f : 1.0f;

    const int row0 = blockIdx.y * 128;
    const int col0 = blockIdx.x * 128;
    const int tid  = threadIdx.x;
    const int lane = tid & 31;
    const int wid  = tid >> 5;
    const int wm   = (wid & 1) * 64;
    const int wn   = (wid >> 1) * 32;
    const int gr   = lane >> 2;
    const int tg   = lane & 3;

    // ldmatrix per-lane offsets (bytes)
    const int mi   = lane >> 3;
    const int lrow = lane & 7;
    const uint32_t a_rl = (uint32_t)(((mi & 1) * 8 + lrow) * TROW_B + (mi >> 1) * 16);
    const uint32_t b_rl = (uint32_t)(((mi >> 1) * 8 + lrow) * TROW_B + (mi & 1) * 16);

    // staging map: idx = tid + i*256 over 2048 chunks (A first 1024, then B)
    int srow[8], sc16[8], sisB[8];
#pragma unroll
    for (int i = 0; i < 8; i++) {
        int idx = tid + i * 256;
        sisB[i] = idx >= 1024;
        int id = idx & 1023;
        srow[i] = id >> 3;  sc16[i] = id & 7;
    }

    auto load_chunk = [&](int kc, int st) {
        const uint32_t base = sbase + (uint32_t)st * STG_BB;
        const int kb = kc * 32;
#pragma unroll
        for (int i = 0; i < 8; i++) {
            uint32_t dst = base + (sisB[i] ? TILE_BB : 0)
                         + (uint32_t)(srow[i] * TROW_B + sc16[i] * 16);
            const float* src = sisB[i]
                ? W   + (col0 + srow[i]) * D_ + kb + sc16[i] * 4
                : g_x + (row0 + srow[i]) * D_ + kb + sc16[i] * 4;
            cpasync16(dst, src);
        }
        cpcommit();
    };

    float acc[4][4][4];
#pragma unroll
    for (int i = 0; i < 4; i++)
#pragma unroll
        for (int j = 0; j < 4; j++)
#pragma unroll
            for (int r = 0; r < 4; r++) acc[i][j][r] = 0.0f;

    load_chunk(0, 0);
    load_chunk(1, 1);

    for (int c = 0; c < NKT; c++) {
        const int st = c % 3;
        cpwait1();           // chunk c landed (chunk c+1 may still fly)
        __syncthreads();
        if (c + 2 < NKT) load_chunk(c + 2, (c + 2) % 3);

        const uint32_t Ast = sbase + (uint32_t)st * STG_BB;
        const uint32_t Bst = Ast + TILE_BB;
#pragma unroll
        for (int ks = 0; ks < 4; ks++) {
            uint32_t a[4][4];
#pragma unroll
            for (int mf = 0; mf < 4; mf++)
                ldsm4(a[mf], Ast + (uint32_t)((wm + mf * 16) * TROW_B + ks * 32) + a_rl);
#pragma unroll
            for (int np = 0; np < 2; np++) {
                uint32_t bb[4];
                ldsm4(bb, Bst + (uint32_t)((wn + np * 16) * TROW_B + ks * 32) + b_rl);
#pragma unroll
                for (int mf = 0; mf < 4; mf++) {
                    mma8(acc[mf][np * 2 + 0], a[mf], bb);
                    mma8(acc[mf][np * 2 + 1], a[mf], bb + 2);
                }
            }
        }
    }

    // epilogue: scatter tf32-rounded into [b][h][s][dk]
#pragma unroll
    for (int mf = 0; mf < 4; mf++) {
#pragma unroll
        for (int rr = 0; rr < 2; rr++) {
            int r = row0 + wm + mf * 16 + gr + rr * 8;
            int b = r >> 11, s = r & (S_ - 1);
#pragma unroll
            for (int nf = 0; nf < 4; nf++) {
                int cc = col0 + wn + nf * 8 + 2 * tg;
                int h = cc >> 6, dk = cc & 63;
                float2 v;
                v.x = tf(acc[mf][nf][rr * 2 + 0] * alpha);
                v.y = tf(acc[mf][nf][rr * 2 + 1] * alpha);
                *(float2*)&C[((b * H_ + h) * S_ + s) * DK_ + dk] = v;
            }
        }
    }
}

// ============================================================================
// Kernel 3: output projection — same engine; A gathered from g_ao; +bias.
// ============================================================================
__global__ void __launch_bounds__(256, 2)
out_proj_mma(const float* __restrict__ bO, float* __restrict__ out)
{
    extern __shared__ float dsm[];
    const uint32_t sbase = (uint32_t)__cvta_generic_to_shared(dsm);
    const int row0 = blockIdx.y * 128;
    const int col0 = blockIdx.x * 128;
    const int tid  = threadIdx.x;
    const int lane = tid & 31;
    const int wid  = tid >> 5;
    const int wm   = (wid & 1) * 64;
    const int wn   = (wid >> 1) * 32;
    const int gr   = lane >> 2;
    const int tg   = lane & 3;

    const int mi   = lane >> 3;
    const int lrow = lane & 7;
    const uint32_t a_rl = (uint32_t)(((mi & 1) * 8 + lrow) * TROW_B + (mi >> 1) * 16);
    const uint32_t b_rl = (uint32_t)(((mi >> 1) * 8 + lrow) * TROW_B + (mi & 1) * 16);

    int srow[8], sc16[8], sisB[8];
#pragma unroll
    for (int i = 0; i < 8; i++) {
        int idx = tid + i * 256;
        sisB[i] = idx >= 1024;
        int id = idx & 1023;
        srow[i] = id >> 3;  sc16[i] = id & 7;
    }

    auto load_chunk = [&](int kc, int st) {
        const uint32_t base = sbase + (uint32_t)st * STG_BB;
        const int kb = kc * 32;
#pragma unroll
        for (int i = 0; i < 8; i++) {
            uint32_t dst = base + (sisB[i] ? TILE_BB : 0)
                         + (uint32_t)(srow[i] * TROW_B + sc16[i] * 16);
            const float* src;
            if (sisB[i]) {
                src = g_wo + (col0 + srow[i]) * D_ + kb + sc16[i] * 4;
            } else {
                int row = row0 + srow[i];
                int b = row >> 11, s = row & (S_ - 1);
                int k = kb + sc16[i] * 4;
                int h = k >> 6, dk = k & 63;
                src = &g_ao[((b * H_ + h) * S_ + s) * DK_ + dk];
            }
            cpasync16(dst, src);
        }
        cpcommit();
    };

    float acc[4][4][4];
#pragma unroll
    for (int i = 0; i < 4; i++)
#pragma unroll
        for (int j = 0; j < 4; j++)
#pragma unroll
            for (int r = 0; r < 4; r++) acc[i][j][r] = 0.0f;

    load_chunk(0, 0);
    load_chunk(1, 1);

    for (int c = 0; c < NKT; c++) {
        const int st = c % 3;
        cpwait1();
        __syncthreads();
        if (c + 2 < NKT) load_chunk(c + 2, (c + 2) % 3);

        const uint32_t Ast = sbase + (uint32_t)st * STG_BB;
        const uint32_t Bst = Ast + TILE_BB;
#pragma unroll
        for (int ks = 0; ks < 4; ks++) {
            uint32_t a[4][4];
#pragma unroll
            for (int mf = 0; mf < 4; mf++)
                ldsm4(a[mf], Ast + (uint32_t)((wm + mf * 16) * TROW_B + ks * 32) + a_rl);
#pragma unroll
            for (int np = 0; np < 2; np++) {
                uint32_t bb[4];
                ldsm4(bb, Bst + (uint32_t)((wn + np * 16) * TROW_B + ks * 32) + b_rl);
#pragma unroll
                for (int mf = 0; mf < 4; mf++) {
                    mma8(acc[mf][np * 2 + 0], a[mf], bb);
                    mma8(acc[mf][np * 2 + 1], a[mf], bb + 2);
                }
            }
        }
    }

#pragma unroll
    for (int mf = 0; mf < 4; mf++) {
#pragma unroll
        for (int rr = 0; rr < 2; rr++) {
            int r = row0 + wm + mf * 16 + gr + rr * 8;
#pragma unroll
            for (int nf = 0; nf < 4; nf++) {
                int cc = col0 + wn + nf * 8 + 2 * tg;
                float2 v;
                v.x = acc[mf][nf][rr * 2 + 0] + bO[cc];
                v.y = acc[mf][nf][rr * 2 + 1] + bO[cc + 1];
                *(float2*)&out[r * D_ + cc] = v;
            }
        }
    }
}

// ============================================================================
// Kernel 2: causal flash attention — UNCHANGED from R10 (BQ=128, reg softmax)
// ============================================================================
#define MASKV   (-3.0e38f)
#define QW      68
#define VW      72
#define QFL     (128 * QW)
#define KFL     (64 * QW)
#define VFL     (64 * VW)
#define KV_FL   (KFL + VFL)
#define ATTN_SMEM_BYTES ((QFL + 2 * KV_FL) * 4)

__global__ void __launch_bounds__(256)
attn_mma()
{
    extern __shared__ float dsm[];
    float* Qs = dsm;

    const int bh = blockIdx.x;
    const int qt = (gridDim.y - 1) - blockIdx.y;
    const float* __restrict__ Kp = g_qp + bh * S_ * DK_;
    const float* __restrict__ Qp = g_kp + bh * S_ * DK_;
    const float* __restrict__ Vp = g_vp + bh * S_ * DK_;
    float* __restrict__ Op = g_ao + bh * S_ * DK_;

    const int t    = threadIdx.x;
    const int lane = t & 31;
    const int wid  = t >> 5;
    const int gr   = lane >> 2;
    const int tg   = lane & 3;
    const int wr   = wid * 16;

    const uint32_t sbase = (uint32_t)__cvta_generic_to_shared(dsm);

    int cr[4], cc[4];
#pragma unroll
    for (int i = 0; i < 4; i++) {
        int f = t + i * 256;
        cr[i] = f >> 4;  cc[i] = (f & 15) * 4;
    }

    auto issue_kv = [&](int st, int kt) {
        const uint32_t sk = sbase + (uint32_t)(QFL + st * KV_FL) * 4u;
        const uint32_t sv = sk + (uint32_t)KFL * 4u;
#pragma unroll
        for (int i = 0; i < 4; i++)
            cpasync16(sk + (uint32_t)(cr[i] * QW + cc[i]) * 4u,
                      Kp + (kt * 64 + cr[i]) * DK_ + cc[i]);
#pragma unroll
        for (int i = 0; i < 4; i++)
            cpasync16(sv + (uint32_t)(cr[i] * VW + cc[i]) * 4u,
                      Vp + (kt * 64 + cr[i]) * DK_ + cc[i]);
        cpcommit();
    };

    {
#pragma unroll
        for (int i = 0; i < 8; i++) {
            int f = t + i * 256;
            int r = f >> 4, c = (f & 15) * 4;
            cpasync16(sbase + (uint32_t)(r * QW + c) * 4u,
                      Qp + (qt * 128 + r) * DK_ + c);
        }
        issue_kv(0, 0);
    }
    cpwait0();
    __syncthreads();

    uint32_t qa[8][4];
#pragma unroll
    for (int ks = 0; ks < 8; ks++) {
        const int kk = ks * 8;
        qa[ks][0] = __float_as_uint(Qs[(wr + gr) * QW + kk + tg]);
        qa[ks][1] = __float_as_uint(Qs[(wr + gr + 8) * QW + kk + tg]);
        qa[ks][2] = __float_as_uint(Qs[(wr + gr) * QW + kk + tg + 4]);
        qa[ks][3] = __float_as_uint(Qs[(wr + gr + 8) * QW + kk + tg + 4]);
    }

    float o[8][4];
#pragma unroll
    for (int nf = 0; nf < 8; nf++)
#pragma unroll
        for (int r = 0; r < 4; r++) o[nf][r] = 0.0f;

    float m0 = MASKV, m1 = MASKV, l0 = 0.0f, l1 = 0.0f;
    const int ri0 = qt * 128 + wr + gr;
    const int ri1 = ri0 + 8;

    const int nkt = 2 * qt + 2;
    for (int kt = 0; kt < nkt; kt++) {
        const int st = kt & 1;
        float* Ks = dsm + QFL + st * KV_FL;
        float* Vs = Ks + KFL;

        cpwait0();
        __syncthreads();
        if (kt + 1 < nkt) issue_kv(st ^ 1, kt + 1);

        float sc[8][4];
#pragma unroll
        for (int nf = 0; nf < 8; nf++)
#pragma unroll
            for (int r = 0; r < 4; r++) sc[nf][r] = 0.0f;

#pragma unroll
        for (int ks = 0; ks < 8; ks++) {
            const int kk = ks * 8;
#pragma unroll
            for (int nf = 0; nf < 8; nf++) {
                uint32_t b[2];
                int n = nf * 8 + gr;
                b[0] = __float_as_uint(Ks[n * QW + kk + tg]);
                b[1] = __float_as_uint(Ks[n * QW + kk + tg + 4]);
                mma8(sc[nf], qa[ks], b);
            }
        }

        if (kt >= nkt - 2) {
#pragma unroll
            for (int nf = 0; nf < 8; nf++) {
                int c0 = kt * 64 + nf * 8 + 2 * tg;
                if (c0 > ri0)     sc[nf][0] = MASKV;
                if (c0 + 1 > ri0) sc[nf][1] = MASKV;
                if (c0 > ri1)     sc[nf][2] = MASKV;
                if (c0 + 1 > ri1) sc[nf][3] = MASKV;
            }
        }

        float tm0 = MASKV, tm1 = MASKV;
#pragma unroll
        for (int nf = 0; nf < 8; nf++) {
            tm0 = fmaxf(tm0, fmaxf(sc[nf][0], sc[nf][1]));
            tm1 = fmaxf(tm1, fmaxf(sc[nf][2], sc[nf][3]));
        }
        tm0 = fmaxf(tm0, __shfl_xor_sync(0xffffffffu, tm0, 1));
        tm0 = fmaxf(tm0, __shfl_xor_sync(0xffffffffu, tm0, 2));
        tm1 = fmaxf(tm1, __shfl_xor_sync(0xffffffffu, tm1, 1));
        tm1 = fmaxf(tm1, __shfl_xor_sync(0xffffffffu, tm1, 2));

        float m0n = fmaxf(m0, tm0), m1n = fmaxf(m1, tm1);
        float corr0 = __expf(m0 - m0n), corr1 = __expf(m1 - m1n);
        float ps0 = 0.0f, ps1 = 0.0f;
#pragma unroll
        for (int nf = 0; nf < 8; nf++) {
            float e0 = __expf(sc[nf][0] - m0n);
            float e1 = __expf(sc[nf][1] - m0n);
            float e2 = __expf(sc[nf][2] - m1n);
            float e3 = __expf(sc[nf][3] - m1n);
            ps0 += e0 + e1; ps1 += e2 + e3;
            sc[nf][0] = tf(e0); sc[nf][1] = tf(e1);
            sc[nf][2] = tf(e2); sc[nf][3] = tf(e3);
        }
        ps0 += __shfl_xor_sync(0xffffffffu, ps0, 1);
        ps0 += __shfl_xor_sync(0xffffffffu, ps0, 2);
        ps1 += __shfl_xor_sync(0xffffffffu, ps1, 1);
        ps1 += __shfl_xor_sync(0xffffffffu, ps1, 2);
        l0 = l0 * corr0 + ps0;  l1 = l1 * corr1 + ps1;
        m0 = m0n;  m1 = m1n;

#pragma unroll
        for (int nf = 0; nf < 8; nf++) {
            o[nf][0] *= corr0; o[nf][1] *= corr0;
            o[nf][2] *= corr1; o[nf][3] *= corr1;
        }

        const int src1 = (lane & ~3) | (tg >> 1);
        const int src2 = src1 + 2;
        const int sel  = tg & 1;
#pragma unroll
        for (int ks = 0; ks < 8; ks++) {
            float v00 = __shfl_sync(0xffffffffu, sc[ks][0], src1);
            float v01 = __shfl_sync(0xffffffffu, sc[ks][1], src1);
            float v10 = __shfl_sync(0xffffffffu, sc[ks][2], src1);
            float v11 = __shfl_sync(0xffffffffu, sc[ks][3], src1);
            float w00 = __shfl_sync(0xffffffffu, sc[ks][0], src2);
            float w01 = __shfl_sync(0xffffffffu, sc[ks][1], src2);
            float w10 = __shfl_sync(0xffffffffu, sc[ks][2], src2);
            float w11 = __shfl_sync(0xffffffffu, sc[ks][3], src2);
            uint32_t a[4];
            a[0] = __float_as_uint(sel ? v01 : v00);
            a[1] = __float_as_uint(sel ? v11 : v10);
            a[2] = __float_as_uint(sel ? w01 : w00);
            a[3] = __float_as_uint(sel ? w11 : w10);
            const int kk = ks * 8;
#pragma unroll
            for (int nf = 0; nf < 8; nf++) {
                uint32_t b[2];
                int n = nf * 8 + gr;
                b[0] = __float_as_uint(Vs[(kk + tg) * VW + n]);
                b[1] = __float_as_uint(Vs[(kk + tg + 4) * VW + n]);
                mma8(o[nf], a, b);
            }
        }
    }

    const float li0 = 1.0f / l0, li1 = 1.0f / l1;
#pragma unroll
    for (int nf = 0; nf < 8; nf++) {
        int c = nf * 8 + 2 * tg;
        float2 v0, v1;
        v0.x = tf(o[nf][0] * li0); v0.y = tf(o[nf][1] * li0);
        v1.x = tf(o[nf][2] * li1); v1.y = tf(o[nf][3] * li1);
        *(float2*)&Op[ri0 * DK_ + c] = v0;
        *(float2*)&Op[ri1 * DK_ + c] = v1;
    }
}

// ============================================================================
// launcher — inputs: 0 X, 1 mask(unused), 2 WQ, 3 WK, 4 WV, 5 WO, 6 bO
// ============================================================================
extern "C" void kernel_launch(void* const* d_in, const int* in_sizes, int n_in,
                              void* d_out, int out_size)
{
    (void)in_sizes; (void)n_in; (void)out_size;
    const float* X  = (const float*)d_in[0];
    const float* WQ = (const float*)d_in[2];
    const float* WK = (const float*)d_in[3];
    const float* WV = (const float*)d_in[4];
    const float* WO = (const float*)d_in[5];
    const float* bO = (const float*)d_in[6];
    float* out = (float*)d_out;

    static bool s_init = false;
    if (!s_init) {
        cudaFuncSetAttribute(proj_qkv_mma,
                             cudaFuncAttributeMaxDynamicSharedMemorySize, GS_SMEM);
        cudaFuncSetAttribute(out_proj_mma,
                             cudaFuncAttributeMaxDynamicSharedMemorySize, GS_SMEM);
        cudaFuncSetAttribute(attn_mma,
                             cudaFuncAttributeMaxDynamicSharedMemorySize, ATTN_SMEM_BYTES);
        s_init = true;
    }

    x_round<<<2048, 256>>>(X);
    {
        dim3 grid(32, 32, 4);
        w_trans<<<grid, dim3(32, 8)>>>(WQ, WK, WV, WO);
    }
    {
        dim3 grid(8, 32, 3);
        proj_qkv_mma<<<grid, 256, GS_SMEM>>>();
    }
    {
        dim3 grid(BH_, S_ / 128);
        attn_mma<<<grid, 256, ATTN_SMEM_BYTES>>>();
    }
    {
        dim3 grid(8, 32);
        out_proj_mma<<<grid, 256, GS_SMEM>>>(bO, out);
    }
}

// round 15
// speedup vs baseline: 1.2490x; 1.0170x over previous
#include <cuda_runtime.h>
#include <stdint.h>

#define B_  2
#define S_  2048
#define D_  1024
#define H_  16
#define DK_ 64
#define N_  (B_ * S_)            // 4096
#define BH_ (B_ * H_)            // 32

// ---------------- scratch (static device globals) ---------------------------
__device__ float g_x [N_ * D_];          // tf32-rounded input (row-major [m][k])
__device__ float g_wq[D_ * D_];          // tf32-rounded TRANSPOSED weights [n][k]
__device__ float g_wk[D_ * D_];
__device__ float g_wv[D_ * D_];
__device__ float g_wo[D_ * D_];
// layout [b][h][s][dk] — written ALREADY tf32-rounded by producer epilogues
__device__ float g_qp[BH_ * S_ * DK_];   // X @ WQ * scale   (key role)
__device__ float g_kp[BH_ * S_ * DK_];   // X @ WK           (query role)
__device__ float g_vp[BH_ * S_ * DK_];   // X @ WV
__device__ float g_ao[BH_ * S_ * DK_];   // attention output

// ---------------- helpers ----------------------------------------------------
__device__ __forceinline__ uint32_t f2tf(float x) {
    uint32_t u; asm("cvt.rna.tf32.f32 %0, %1;" : "=r"(u) : "f"(x)); return u;
}
__device__ __forceinline__ float tf(float x) { return __uint_as_float(f2tf(x)); }

__device__ __forceinline__ void mma8(float* d, const uint32_t* a, const uint32_t* b) {
    asm volatile("mma.sync.aligned.m16n8k8.row.col.f32.tf32.tf32.f32 "
                 "{%0,%1,%2,%3}, {%4,%5,%6,%7}, {%8,%9}, {%0,%1,%2,%3};\n"
                 : "+f"(d[0]), "+f"(d[1]), "+f"(d[2]), "+f"(d[3])
                 : "r"(a[0]), "r"(a[1]), "r"(a[2]), "r"(a[3]),
                   "r"(b[0]), "r"(b[1]));
}

__device__ __forceinline__ void ldsm4(uint32_t* r, uint32_t addr) {
    asm volatile("ldmatrix.sync.aligned.m8n8.x4.shared.b16 {%0,%1,%2,%3}, [%4];"
                 : "=r"(r[0]), "=r"(r[1]), "=r"(r[2]), "=r"(r[3]) : "r"(addr));
}

__device__ __forceinline__ void cpasync16(uint32_t smem_dst, const void* gptr) {
    asm volatile("cp.async.cg.shared.global [%0], [%1], 16;\n"
                 :: "r"(smem_dst), "l"(gptr));
}
__device__ __forceinline__ void cpcommit() {
    asm volatile("cp.async.commit_group;\n");
}
__device__ __forceinline__ void cpwait0() {
    asm volatile("cp.async.wait_group 0;\n");
}
__device__ __forceinline__ void cpwait1() {
    asm volatile("cp.async.wait_group 1;\n");
}

// ============================================================================
// Kernel 0a: X rounding (grid-stride)
// ============================================================================
#define XF4 ((N_ * D_) / 4)
__global__ void x_round(const float* __restrict__ X)
{
    int i = blockIdx.x * blockDim.x + threadIdx.x;
    int stride = gridDim.x * blockDim.x;
    const float4* s4 = (const float4*)X;
    float4* d4 = (float4*)g_x;
    for (; i < XF4; i += stride) {
        float4 v = s4[i];
        v.x = tf(v.x); v.y = tf(v.y); v.z = tf(v.z); v.w = tf(v.w);
        d4[i] = v;
    }
}

// ============================================================================
// Kernel 0b: weight transpose + round: dst[n][k] = tf(src[k][n])
// ============================================================================
__global__ void w_trans(const float* __restrict__ WQ, const float* __restrict__ WK,
                        const float* __restrict__ WV, const float* __restrict__ WO)
{
    const int mat = blockIdx.z;
    const float* __restrict__ src = (mat == 0) ? WQ : (mat == 1) ? WK : (mat == 2) ? WV : WO;
    float* __restrict__ dst = (mat == 0) ? g_wq : (mat == 1) ? g_wk : (mat == 2) ? g_wv : g_wo;

    __shared__ float tile[32][33];
    const int n0 = blockIdx.x * 32, k0 = blockIdx.y * 32;
    const int tx = threadIdx.x, ty = threadIdx.y;
#pragma unroll
    for (int i = 0; i < 4; i++)
        tile[ty + i * 8][tx] = tf(src[(k0 + ty + i * 8) * D_ + n0 + tx]);
    __syncthreads();
#pragma unroll
    for (int i = 0; i < 4; i++)
        dst[(n0 + ty + i * 8) * D_ + k0 + tx] = tile[tx][ty + i * 8];
}

// ---------------- GEMM geometry ----------------------------------------------
#define TROW_B   144                        // bytes per staged row
#define TILE_FL  (128 * 36)                 // floats per tile
#define TILE_BB  (TILE_FL * 4)              // 18432 B
#define STG_BB   (2 * TILE_BB)              // A+B per stage
#define GS_SMEM  (3 * STG_BB)               // 110592 B
#define NKT      32                         // 1024 / 32

// ============================================================================
// Kernel 1: QKV projection — ldmatrix + mma.sync, 3-stage ring, 1 sync/ktile.
// ============================================================================
__global__ void __launch_bounds__(256, 2)
proj_qkv_mma()
{
    extern __shared__ float dsm[];
    const uint32_t sbase = (uint32_t)__cvta_generic_to_shared(dsm);
    const int mat = blockIdx.z;
    const float* __restrict__ W = (mat == 0) ? g_wq : (mat == 1) ? g_wk : g_wv;
    float* __restrict__ C = (mat == 0) ? g_qp : (mat == 1) ? g_kp : g_vp;
    const float alpha = (mat == 0) ? 0.125f : 1.0f;

    const int row0 = blockIdx.y * 128;
    const int col0 = blockIdx.x * 128;
    const int tid  = threadIdx.x;
    const int lane = tid & 31;
    const int wid  = tid >> 5;
    const int wm   = (wid & 1) * 64;
    const int wn   = (wid >> 1) * 32;
    const int gr   = lane >> 2;
    const int tg   = lane & 3;

    const int mi   = lane >> 3;
    const int lrow = lane & 7;
    const uint32_t a_rl = (uint32_t)(((mi & 1) * 8 + lrow) * TROW_B + (mi >> 1) * 16);
    const uint32_t b_rl = (uint32_t)(((mi >> 1) * 8 + lrow) * TROW_B + (mi & 1) * 16);

    int srow[8], sc16[8], sisB[8];
#pragma unroll
    for (int i = 0; i < 8; i++) {
        int idx = tid + i * 256;
        sisB[i] = idx >= 1024;
        int id = idx & 1023;
        srow[i] = id >> 3;  sc16[i] = id & 7;
    }

    auto load_chunk = [&](int kc, int st) {
        const uint32_t base = sbase + (uint32_t)st * STG_BB;
        const int kb = kc * 32;
#pragma unroll
        for (int i = 0; i < 8; i++) {
            uint32_t dst = base + (sisB[i] ? TILE_BB : 0)
                         + (uint32_t)(srow[i] * TROW_B + sc16[i] * 16);
            const float* src = sisB[i]
                ? W   + (col0 + srow[i]) * D_ + kb + sc16[i] * 4
                : g_x + (row0 + srow[i]) * D_ + kb + sc16[i] * 4;
            cpasync16(dst, src);
        }
        cpcommit();
    };

    float acc[4][4][4];
#pragma unroll
    for (int i = 0; i < 4; i++)
#pragma unroll
        for (int j = 0; j < 4; j++)
#pragma unroll
            for (int r = 0; r < 4; r++) acc[i][j][r] = 0.0f;

    load_chunk(0, 0);
    load_chunk(1, 1);

    for (int c = 0; c < NKT; c++) {
        const int st = c % 3;
        cpwait1();
        __syncthreads();
        if (c + 2 < NKT) load_chunk(c + 2, (c + 2) % 3);

        const uint32_t Ast = sbase + (uint32_t)st * STG_BB;
        const uint32_t Bst = Ast + TILE_BB;
#pragma unroll
        for (int ks = 0; ks < 4; ks++) {
            uint32_t a[4][4];
#pragma unroll
            for (int mf = 0; mf < 4; mf++)
                ldsm4(a[mf], Ast + (uint32_t)((wm + mf * 16) * TROW_B + ks * 32) + a_rl);
#pragma unroll
            for (int np = 0; np < 2; np++) {
                uint32_t bb[4];
                ldsm4(bb, Bst + (uint32_t)((wn + np * 16) * TROW_B + ks * 32) + b_rl);
#pragma unroll
                for (int mf = 0; mf < 4; mf++) {
                    mma8(acc[mf][np * 2 + 0], a[mf], bb);
                    mma8(acc[mf][np * 2 + 1], a[mf], bb + 2);
                }
            }
        }
    }

#pragma unroll
    for (int mf = 0; mf < 4; mf++) {
#pragma unroll
        for (int rr = 0; rr < 2; rr++) {
            int r = row0 + wm + mf * 16 + gr + rr * 8;
            int b = r >> 11, s = r & (S_ - 1);
#pragma unroll
            for (int nf = 0; nf < 4; nf++) {
                int cc = col0 + wn + nf * 8 + 2 * tg;
                int h = cc >> 6, dk = cc & 63;
                float2 v;
                v.x = tf(acc[mf][nf][rr * 2 + 0] * alpha);
                v.y = tf(acc[mf][nf][rr * 2 + 1] * alpha);
                *(float2*)&C[((b * H_ + h) * S_ + s) * DK_ + dk] = v;
            }
        }
    }
}

// ============================================================================
// Kernel 3: output projection — same engine; A gathered from g_ao; +bias.
// ============================================================================
__global__ void __launch_bounds__(256, 2)
out_proj_mma(const float* __restrict__ bO, float* __restrict__ out)
{
    extern __shared__ float dsm[];
    const uint32_t sbase = (uint32_t)__cvta_generic_to_shared(dsm);
    const int row0 = blockIdx.y * 128;
    const int col0 = blockIdx.x * 128;
    const int tid  = threadIdx.x;
    const int lane = tid & 31;
    const int wid  = tid >> 5;
    const int wm   = (wid & 1) * 64;
    const int wn   = (wid >> 1) * 32;
    const int gr   = lane >> 2;
    const int tg   = lane & 3;

    const int mi   = lane >> 3;
    const int lrow = lane & 7;
    const uint32_t a_rl = (uint32_t)(((mi & 1) * 8 + lrow) * TROW_B + (mi >> 1) * 16);
    const uint32_t b_rl = (uint32_t)(((mi >> 1) * 8 + lrow) * TROW_B + (mi & 1) * 16);

    int srow[8], sc16[8], sisB[8];
#pragma unroll
    for (int i = 0; i < 8; i++) {
        int idx = tid + i * 256;
        sisB[i] = idx >= 1024;
        int id = idx & 1023;
        srow[i] = id >> 3;  sc16[i] = id & 7;
    }

    auto load_chunk = [&](int kc, int st) {
        const uint32_t base = sbase + (uint32_t)st * STG_BB;
        const int kb = kc * 32;
#pragma unroll
        for (int i = 0; i < 8; i++) {
            uint32_t dst = base + (sisB[i] ? TILE_BB : 0)
                         + (uint32_t)(srow[i] * TROW_B + sc16[i] * 16);
            const float* src;
            if (sisB[i]) {
                src = g_wo + (col0 + srow[i]) * D_ + kb + sc16[i] * 4;
            } else {
                int row = row0 + srow[i];
                int b = row >> 11, s = row & (S_ - 1);
                int k = kb + sc16[i] * 4;
                int h = k >> 6, dk = k & 63;
                src = &g_ao[((b * H_ + h) * S_ + s) * DK_ + dk];
            }
            cpasync16(dst, src);
        }
        cpcommit();
    };

    float acc[4][4][4];
#pragma unroll
    for (int i = 0; i < 4; i++)
#pragma unroll
        for (int j = 0; j < 4; j++)
#pragma unroll
            for (int r = 0; r < 4; r++) acc[i][j][r] = 0.0f;

    load_chunk(0, 0);
    load_chunk(1, 1);

    for (int c = 0; c < NKT; c++) {
        const int st = c % 3;
        cpwait1();
        __syncthreads();
        if (c + 2 < NKT) load_chunk(c + 2, (c + 2) % 3);

        const uint32_t Ast = sbase + (uint32_t)st * STG_BB;
        const uint32_t Bst = Ast + TILE_BB;
#pragma unroll
        for (int ks = 0; ks < 4; ks++) {
            uint32_t a[4][4];
#pragma unroll
            for (int mf = 0; mf < 4; mf++)
                ldsm4(a[mf], Ast + (uint32_t)((wm + mf * 16) * TROW_B + ks * 32) + a_rl);
#pragma unroll
            for (int np = 0; np < 2; np++) {
                uint32_t bb[4];
                ldsm4(bb, Bst + (uint32_t)((wn + np * 16) * TROW_B + ks * 32) + b_rl);
#pragma unroll
                for (int mf = 0; mf < 4; mf++) {
                    mma8(acc[mf][np * 2 + 0], a[mf], bb);
                    mma8(acc[mf][np * 2 + 1], a[mf], bb + 2);
                }
            }
        }
    }

#pragma unroll
    for (int mf = 0; mf < 4; mf++) {
#pragma unroll
        for (int rr = 0; rr < 2; rr++) {
            int r = row0 + wm + mf * 16 + gr + rr * 8;
#pragma unroll
            for (int nf = 0; nf < 4; nf++) {
                int cc = col0 + wn + nf * 8 + 2 * tg;
                float2 v;
                v.x = acc[mf][nf][rr * 2 + 0] + bO[cc];
                v.y = acc[mf][nf][rr * 2 + 1] + bO[cc + 1];
                *(float2*)&out[r * D_ + cc] = v;
            }
        }
    }
}

// ============================================================================
// Kernel 2: causal flash attention — BQ=128, register softmax.
// K b-fragments for S=QK^T via ldmatrix.x4; pairing matches the GEMM engine:
// {kb[0],kb[1]} = rows n0..n0+7, {kb[2],kb[3]} = rows n0+8..n0+15.
// ============================================================================
#define MASKV   (-3.0e38f)
#define QW      68
#define VW      72
#define QWB     (QW * 4)                    // 272 B row stride (K/Q tiles)
#define QFL     (128 * QW)
#define KFL     (64 * QW)
#define VFL     (64 * VW)
#define KV_FL   (KFL + VFL)
#define ATTN_SMEM_BYTES ((QFL + 2 * KV_FL) * 4)

__global__ void __launch_bounds__(256)
attn_mma()
{
    extern __shared__ float dsm[];
    float* Qs = dsm;

    const int bh = blockIdx.x;
    const int qt = (gridDim.y - 1) - blockIdx.y;
    const float* __restrict__ Kp = g_qp + bh * S_ * DK_;
    const float* __restrict__ Qp = g_kp + bh * S_ * DK_;
    const float* __restrict__ Vp = g_vp + bh * S_ * DK_;
    float* __restrict__ Op = g_ao + bh * S_ * DK_;

    const int t    = threadIdx.x;
    const int lane = t & 31;
    const int wid  = t >> 5;
    const int gr   = lane >> 2;
    const int tg   = lane & 3;
    const int wr   = wid * 16;

    const uint32_t sbase = (uint32_t)__cvta_generic_to_shared(dsm);

    const int mi   = lane >> 3;
    const int lrow = lane & 7;
    const uint32_t kb_rl = (uint32_t)(((mi >> 1) * 8 + lrow) * QWB + (mi & 1) * 16);

    int cr[4], cc[4];
#pragma unroll
    for (int i = 0; i < 4; i++) {
        int f = t + i * 256;
        cr[i] = f >> 4;  cc[i] = (f & 15) * 4;
    }

    auto issue_kv = [&](int st, int kt) {
        const uint32_t sk = sbase + (uint32_t)(QFL + st * KV_FL) * 4u;
        const uint32_t sv = sk + (uint32_t)KFL * 4u;
#pragma unroll
        for (int i = 0; i < 4; i++)
            cpasync16(sk + (uint32_t)(cr[i] * QW + cc[i]) * 4u,
                      Kp + (kt * 64 + cr[i]) * DK_ + cc[i]);
#pragma unroll
        for (int i = 0; i < 4; i++)
            cpasync16(sv + (uint32_t)(cr[i] * VW + cc[i]) * 4u,
                      Vp + (kt * 64 + cr[i]) * DK_ + cc[i]);
        cpcommit();
    };

    {
#pragma unroll
        for (int i = 0; i < 8; i++) {
            int f = t + i * 256;
            int r = f >> 4, c = (f & 15) * 4;
            cpasync16(sbase + (uint32_t)(r * QW + c) * 4u,
                      Qp + (qt * 128 + r) * DK_ + c);
        }
        issue_kv(0, 0);
    }
    cpwait0();
    __syncthreads();

    uint32_t qa[8][4];
#pragma unroll
    for (int ks = 0; ks < 8; ks++) {
        const int kk = ks * 8;
        qa[ks][0] = __float_as_uint(Qs[(wr + gr) * QW + kk + tg]);
        qa[ks][1] = __float_as_uint(Qs[(wr + gr + 8) * QW + kk + tg]);
        qa[ks][2] = __float_as_uint(Qs[(wr + gr) * QW + kk + tg + 4]);
        qa[ks][3] = __float_as_uint(Qs[(wr + gr + 8) * QW + kk + tg + 4]);
    }

    float o[8][4];
#pragma unroll
    for (int nf = 0; nf < 8; nf++)
#pragma unroll
        for (int r = 0; r < 4; r++) o[nf][r] = 0.0f;

    float m0 = MASKV, m1 = MASKV, l0 = 0.0f, l1 = 0.0f;
    const int ri0 = qt * 128 + wr + gr;
    const int ri1 = ri0 + 8;

    const int nkt = 2 * qt + 2;
    for (int kt = 0; kt < nkt; kt++) {
        const int st = kt & 1;
        float* Vs = dsm + QFL + st * KV_FL + KFL;
        const uint32_t KsAddr = sbase + (uint32_t)(QFL + st * KV_FL) * 4u;

        cpwait0();
        __syncthreads();
        if (kt + 1 < nkt) issue_kv(st ^ 1, kt + 1);

        // ---- S = Q @ K^T (K b-frags via ldmatrix; pairing = GEMM convention) ----
        float sc[8][4];
#pragma unroll
        for (int nf = 0; nf < 8; nf++)
#pragma unroll
            for (int r = 0; r < 4; r++) sc[nf][r] = 0.0f;

#pragma unroll
        for (int ks = 0; ks < 8; ks++) {
#pragma unroll
            for (int ng = 0; ng < 4; ng++) {
                uint32_t kb[4];
                ldsm4(kb, KsAddr + (uint32_t)(ng * 16) * QWB
                          + (uint32_t)(ks * 32) + kb_rl);
                mma8(sc[2 * ng + 0], qa[ks], kb);       // n = ng*16 + gr
                mma8(sc[2 * ng + 1], qa[ks], kb + 2);   // n = ng*16 + 8 + gr
            }
        }

        if (kt >= nkt - 2) {
#pragma unroll
            for (int nf = 0; nf < 8; nf++) {
                int c0 = kt * 64 + nf * 8 + 2 * tg;
                if (c0 > ri0)     sc[nf][0] = MASKV;
                if (c0 + 1 > ri0) sc[nf][1] = MASKV;
                if (c0 > ri1)     sc[nf][2] = MASKV;
                if (c0 + 1 > ri1) sc[nf][3] = MASKV;
            }
        }

        float tm0 = MASKV, tm1 = MASKV;
#pragma unroll
        for (int nf = 0; nf < 8; nf++) {
            tm0 = fmaxf(tm0, fmaxf(sc[nf][0], sc[nf][1]));
            tm1 = fmaxf(tm1, fmaxf(sc[nf][2], sc[nf][3]));
        }
        tm0 = fmaxf(tm0, __shfl_xor_sync(0xffffffffu, tm0, 1));
        tm0 = fmaxf(tm0, __shfl_xor_sync(0xffffffffu, tm0, 2));
        tm1 = fmaxf(tm1, __shfl_xor_sync(0xffffffffu, tm1, 1));
        tm1 = fmaxf(tm1, __shfl_xor_sync(0xffffffffu, tm1, 2));

        float m0n = fmaxf(m0, tm0), m1n = fmaxf(m1, tm1);
        float corr0 = __expf(m0 - m0n), corr1 = __expf(m1 - m1n);
        float ps0 = 0.0f, ps1 = 0.0f;
#pragma unroll
        for (int nf = 0; nf < 8; nf++) {
            float e0 = __expf(sc[nf][0] - m0n);
            float e1 = __expf(sc[nf][1] - m0n);
            float e2 = __expf(sc[nf][2] - m1n);
            float e3 = __expf(sc[nf][3] - m1n);
            ps0 += e0 + e1; ps1 += e2 + e3;
            sc[nf][0] = tf(e0); sc[nf][1] = tf(e1);
            sc[nf][2] = tf(e2); sc[nf][3] = tf(e3);
        }
        ps0 += __shfl_xor_sync(0xffffffffu, ps0, 1);
        ps0 += __shfl_xor_sync(0xffffffffu, ps0, 2);
        ps1 += __shfl_xor_sync(0xffffffffu, ps1, 1);
        ps1 += __shfl_xor_sync(0xffffffffu, ps1, 2);
        l0 = l0 * corr0 + ps0;  l1 = l1 * corr1 + ps1;
        m0 = m0n;  m1 = m1n;

#pragma unroll
        for (int nf = 0; nf < 8; nf++) {
            o[nf][0] *= corr0; o[nf][1] *= corr0;
            o[nf][2] *= corr1; o[nf][3] *= corr1;
        }

        const int src1 = (lane & ~3) | (tg >> 1);
        const int src2 = src1 + 2;
        const int sel  = tg & 1;
#pragma unroll
        for (int ks = 0; ks < 8; ks++) {
            float v00 = __shfl_sync(0xffffffffu, sc[ks][0], src1);
            float v01 = __shfl_sync(0xffffffffu, sc[ks][1], src1);
            float v10 = __shfl_sync(0xffffffffu, sc[ks][2], src1);
            float v11 = __shfl_sync(0xffffffffu, sc[ks][3], src1);
            float w00 = __shfl_sync(0xffffffffu, sc[ks][0], src2);
            float w01 = __shfl_sync(0xffffffffu, sc[ks][1], src2);
            float w10 = __shfl_sync(0xffffffffu, sc[ks][2], src2);
            float w11 = __shfl_sync(0xffffffffu, sc[ks][3], src2);
            uint32_t a[4];
            a[0] = __float_as_uint(sel ? v01 : v00);
            a[1] = __float_as_uint(sel ? v11 : v10);
            a[2] = __float_as_uint(sel ? w01 : w00);
            a[3] = __float_as_uint(sel ? w11 : w10);
            const int kk = ks * 8;
#pragma unroll
            for (int nf = 0; nf < 8; nf++) {
                uint32_t b[2];
                int n = nf * 8 + gr;
                b[0] = __float_as_uint(Vs[(kk + tg) * VW + n]);
                b[1] = __float_as_uint(Vs[(kk + tg + 4) * VW + n]);
                mma8(o[nf], a, b);
            }
        }
    }

    const float li0 = 1.0f / l0, li1 = 1.0f / l1;
#pragma unroll
    for (int nf = 0; nf < 8; nf++) {
        int c = nf * 8 + 2 * tg;
        float2 v0, v1;
        v0.x = tf(o[nf][0] * li0); v0.y = tf(o[nf][1] * li0);
        v1.x = tf(o[nf][2] * li1); v1.y = tf(o[nf][3] * li1);
        *(float2*)&Op[ri0 * DK_ + c] = v0;
        *(float2*)&Op[ri1 * DK_ + c] = v1;
    }
}

// ============================================================================
// launcher — inputs: 0 X, 1 mask(unused), 2 WQ, 3 WK, 4 WV, 5 WO, 6 bO
// ============================================================================
extern "C" void kernel_launch(void* const* d_in, const int* in_sizes, int n_in,
                              void* d_out, int out_size)
{
    (void)in_sizes; (void)n_in; (void)out_size;
    const float* X  = (const float*)d_in[0];
    const float* WQ = (const float*)d_in[2];
    const float* WK = (const float*)d_in[3];
    const float* WV = (const float*)d_in[4];
    const float* WO = (const float*)d_in[5];
    const float* bO = (const float*)d_in[6];
    float* out = (float*)d_out;

    static bool s_init = false;
    if (!s_init) {
        cudaFuncSetAttribute(proj_qkv_mma,
                             cudaFuncAttributeMaxDynamicSharedMemorySize, GS_SMEM);
        cudaFuncSetAttribute(out_proj_mma,
                             cudaFuncAttributeMaxDynamicSharedMemorySize, GS_SMEM);
        cudaFuncSetAttribute(attn_mma,
                             cudaFuncAttributeMaxDynamicSharedMemorySize, ATTN_SMEM_BYTES);
        s_init = true;
    }

    x_round<<<2048, 256>>>(X);
    {
        dim3 grid(32, 32, 4);
        w_trans<<<grid, dim3(32, 8)>>>(WQ, WK, WV, WO);
    }
    {
        dim3 grid(8, 32, 3);
        proj_qkv_mma<<<grid, 256, GS_SMEM>>>();
    }
    {
        dim3 grid(BH_, S_ / 128);
        attn_mma<<<grid, 256, ATTN_SMEM_BYTES>>>();
    }
    {
        dim3 grid(8, 32);
        out_proj_mma<<<grid, 256, GS_SMEM>>>(bO, out);
    }
}

// round 17
// speedup vs baseline: 1.2616x; 1.0101x over previous
#include <cuda_runtime.h>
#include <stdint.h>

#define B_  2
#define S_  2048
#define D_  1024
#define H_  16
#define DK_ 64
#define N_  (B_ * S_)            // 4096
#define BH_ (B_ * H_)            // 32

// ---------------- scratch (static device globals) ---------------------------
__device__ float g_x [N_ * D_];          // tf32-rounded input (row-major [m][k])
__device__ float g_wq[D_ * D_];          // tf32-rounded TRANSPOSED weights [n][k]
__device__ float g_wk[D_ * D_];
__device__ float g_wv[D_ * D_];
__device__ float g_wo[D_ * D_];
// layout [b][h][s][dk] — written ALREADY tf32-rounded by producer epilogues
__device__ float g_qp[BH_ * S_ * DK_];   // X @ WQ * scale   (key role)
__device__ float g_kp[BH_ * S_ * DK_];   // X @ WK           (query role)
__device__ float g_vp[BH_ * S_ * DK_];   // X @ WV
__device__ float g_vt[BH_ * DK_ * S_];   // V transposed: [bh][dk][s]
__device__ float g_ao[BH_ * S_ * DK_];   // attention output

// ---------------- helpers ----------------------------------------------------
__device__ __forceinline__ uint32_t f2tf(float x) {
    uint32_t u; asm("cvt.rna.tf32.f32 %0, %1;" : "=r"(u) : "f"(x)); return u;
}
__device__ __forceinline__ float tf(float x) { return __uint_as_float(f2tf(x)); }

__device__ __forceinline__ void mma8(float* d, const uint32_t* a, const uint32_t* b) {
    asm volatile("mma.sync.aligned.m16n8k8.row.col.f32.tf32.tf32.f32 "
                 "{%0,%1,%2,%3}, {%4,%5,%6,%7}, {%8,%9}, {%0,%1,%2,%3};\n"
                 : "+f"(d[0]), "+f"(d[1]), "+f"(d[2]), "+f"(d[3])
                 : "r"(a[0]), "r"(a[1]), "r"(a[2]), "r"(a[3]),
                   "r"(b[0]), "r"(b[1]));
}

__device__ __forceinline__ void ldsm4(uint32_t* r, uint32_t addr) {
    asm volatile("ldmatrix.sync.aligned.m8n8.x4.shared.b16 {%0,%1,%2,%3}, [%4];"
                 : "=r"(r[0]), "=r"(r[1]), "=r"(r[2]), "=r"(r[3]) : "r"(addr));
}

__device__ __forceinline__ void cpasync16(uint32_t smem_dst, const void* gptr) {
    asm volatile("cp.async.cg.shared.global [%0], [%1], 16;\n"
                 :: "r"(smem_dst), "l"(gptr));
}
__device__ __forceinline__ void cpcommit() {
    asm volatile("cp.async.commit_group;\n");
}
__device__ __forceinline__ void cpwait0() {
    asm volatile("cp.async.wait_group 0;\n");
}
__device__ __forceinline__ void cpwait1() {
    asm volatile("cp.async.wait_group 1;\n");
}

// ============================================================================
// Kernel 0a: X rounding (grid-stride)
// ============================================================================
#define XF4 ((N_ * D_) / 4)
__global__ void x_round(const float* __restrict__ X)
{
    int i = blockIdx.x * blockDim.x + threadIdx.x;
    int stride = gridDim.x * blockDim.x;
    const float4* s4 = (const float4*)X;
    float4* d4 = (float4*)g_x;
    for (; i < XF4; i += stride) {
        float4 v = s4[i];
        v.x = tf(v.x); v.y = tf(v.y); v.z = tf(v.z); v.w = tf(v.w);
        d4[i] = v;
    }
}

// ============================================================================
// Kernel 0b: weight transpose + round: dst[n][k] = tf(src[k][n])
// ============================================================================
__global__ void w_trans(const float* __restrict__ WQ, const float* __restrict__ WK,
                        const float* __restrict__ WV, const float* __restrict__ WO)
{
    const int mat = blockIdx.z;
    const float* __restrict__ src = (mat == 0) ? WQ : (mat == 1) ? WK : (mat == 2) ? WV : WO;
    float* __restrict__ dst = (mat == 0) ? g_wq : (mat == 1) ? g_wk : (mat == 2) ? g_wv : g_wo;

    __shared__ float tile[32][33];
    const int n0 = blockIdx.x * 32, k0 = blockIdx.y * 32;
    const int tx = threadIdx.x, ty = threadIdx.y;
#pragma unroll
    for (int i = 0; i < 4; i++)
        tile[ty + i * 8][tx] = tf(src[(k0 + ty + i * 8) * D_ + n0 + tx]);
    __syncthreads();
#pragma unroll
    for (int i = 0; i < 4; i++)
        dst[(n0 + ty + i * 8) * D_ + k0 + tx] = tile[tx][ty + i * 8];
}

// ============================================================================
// Kernel 2a: V transpose: g_vt[bh][dk][s] = g_vp[bh][s][dk]
// grid (BH, S/32, DK/32), block (32, 8)
// ============================================================================
__global__ void v_trans()
{
    __shared__ float tile[32][33];
    const int bh = blockIdx.x;
    const int s0 = blockIdx.y * 32;
    const int d0 = blockIdx.z * 32;
    const int tx = threadIdx.x, ty = threadIdx.y;
#pragma unroll
    for (int i = 0; i < 4; i++)
        tile[ty + i * 8][tx] = g_vp[(bh * S_ + s0 + ty + i * 8) * DK_ + d0 + tx];
    __syncthreads();
#pragma unroll
    for (int i = 0; i < 4; i++)
        g_vt[(bh * DK_ + d0 + ty + i * 8) * S_ + s0 + tx] = tile[tx][ty + i * 8];
}

// ---------------- GEMM geometry ----------------------------------------------
#define TROW_B   144                        // bytes per staged row
#define TILE_FL  (128 * 36)                 // floats per tile
#define TILE_BB  (TILE_FL * 4)              // 18432 B
#define STG_BB   (2 * TILE_BB)              // A+B per stage
#define GS_SMEM  (3 * STG_BB)               // 110592 B
#define NKT      32                         // 1024 / 32

// ============================================================================
// Kernel 1: QKV projection — ldmatrix + mma.sync, 3-stage ring, 1 sync/ktile.
// ============================================================================
__global__ void __launch_bounds__(256, 2)
proj_qkv_mma()
{
    extern __shared__ float dsm[];
    const uint32_t sbase = (uint32_t)__cvta_generic_to_shared(dsm);
    const int mat = blockIdx.z;
    const float* __restrict__ W = (mat == 0) ? g_wq : (mat == 1) ? g_wk : g_wv;
    float* __restrict__ C = (mat == 0) ? g_qp : (mat == 1) ? g_kp : g_vp;
    const float alpha = (mat == 0) ? 0.125f : 1.0f;

    const int row0 = blockIdx.y * 128;
    const int col0 = blockIdx.x * 128;
    const int tid  = threadIdx.x;
    const int lane = tid & 31;
    const int wid  = tid >> 5;
    const int wm   = (wid & 1) * 64;
    const int wn   = (wid >> 1) * 32;
    const int gr   = lane >> 2;
    const int tg   = lane & 3;

    const int mi   = lane >> 3;
    const int lrow = lane & 7;
    const uint32_t a_rl = (uint32_t)(((mi & 1) * 8 + lrow) * TROW_B + (mi >> 1) * 16);
    const uint32_t b_rl = (uint32_t)(((mi >> 1) * 8 + lrow) * TROW_B + (mi & 1) * 16);

    int srow[8], sc16[8], sisB[8];
#pragma unroll
    for (int i = 0; i < 8; i++) {
        int idx = tid + i * 256;
        sisB[i] = idx >= 1024;
        int id = idx & 1023;
        srow[i] = id >> 3;  sc16[i] = id & 7;
    }

    auto load_chunk = [&](int kc, int st) {
        const uint32_t base = sbase + (uint32_t)st * STG_BB;
        const int kb = kc * 32;
#pragma unroll
        for (int i = 0; i < 8; i++) {
            uint32_t dst = base + (sisB[i] ? TILE_BB : 0)
                         + (uint32_t)(srow[i] * TROW_B + sc16[i] * 16);
            const float* src = sisB[i]
                ? W   + (col0 + srow[i]) * D_ + kb + sc16[i] * 4
                : g_x + (row0 + srow[i]) * D_ + kb + sc16[i] * 4;
            cpasync16(dst, src);
        }
        cpcommit();
    };

    float acc[4][4][4];
#pragma unroll
    for (int i = 0; i < 4; i++)
#pragma unroll
        for (int j = 0; j < 4; j++)
#pragma unroll
            for (int r = 0; r < 4; r++) acc[i][j][r] = 0.0f;

    load_chunk(0, 0);
    load_chunk(1, 1);

    for (int c = 0; c < NKT; c++) {
        const int st = c % 3;
        cpwait1();
        __syncthreads();
        if (c + 2 < NKT) load_chunk(c + 2, (c + 2) % 3);

        const uint32_t Ast = sbase + (uint32_t)st * STG_BB;
        const uint32_t Bst = Ast + TILE_BB;
#pragma unroll
        for (int ks = 0; ks < 4; ks++) {
            uint32_t a[4][4];
#pragma unroll
            for (int mf = 0; mf < 4; mf++)
                ldsm4(a[mf], Ast + (uint32_t)((wm + mf * 16) * TROW_B + ks * 32) + a_rl);
#pragma unroll
            for (int np = 0; np < 2; np++) {
                uint32_t bb[4];
                ldsm4(bb, Bst + (uint32_t)((wn + np * 16) * TROW_B + ks * 32) + b_rl);
#pragma unroll
                for (int mf = 0; mf < 4; mf++) {
                    mma8(acc[mf][np * 2 + 0], a[mf], bb);
                    mma8(acc[mf][np * 2 + 1], a[mf], bb + 2);
                }
            }
        }
    }

#pragma unroll
    for (int mf = 0; mf < 4; mf++) {
#pragma unroll
        for (int rr = 0; rr < 2; rr++) {
            int r = row0 + wm + mf * 16 + gr + rr * 8;
            int b = r >> 11, s = r & (S_ - 1);
#pragma unroll
            for (int nf = 0; nf < 4; nf++) {
                int cc = col0 + wn + nf * 8 + 2 * tg;
                int h = cc >> 6, dk = cc & 63;
                float2 v;
                v.x = tf(acc[mf][nf][rr * 2 + 0] * alpha);
                v.y = tf(acc[mf][nf][rr * 2 + 1] * alpha);
                *(float2*)&C[((b * H_ + h) * S_ + s) * DK_ + dk] = v;
            }
        }
    }
}

// ============================================================================
// Kernel 3: output projection — same engine; A gathered from g_ao; +bias.
// ============================================================================
__global__ void __launch_bounds__(256, 2)
out_proj_mma(const float* __restrict__ bO, float* __restrict__ out)
{
    extern __shared__ float dsm[];
    const uint32_t sbase = (uint32_t)__cvta_generic_to_shared(dsm);
    const int row0 = blockIdx.y * 128;
    const int col0 = blockIdx.x * 128;
    const int tid  = threadIdx.x;
    const int lane = tid & 31;
    const int wid  = tid >> 5;
    const int wm   = (wid & 1) * 64;
    const int wn   = (wid >> 1) * 32;
    const int gr   = lane >> 2;
    const int tg   = lane & 3;

    const int mi   = lane >> 3;
    const int lrow = lane & 7;
    const uint32_t a_rl = (uint32_t)(((mi & 1) * 8 + lrow) * TROW_B + (mi >> 1) * 16);
    const uint32_t b_rl = (uint32_t)(((mi >> 1) * 8 + lrow) * TROW_B + (mi & 1) * 16);

    int srow[8], sc16[8], sisB[8];
#pragma unroll
    for (int i = 0; i < 8; i++) {
        int idx = tid + i * 256;
        sisB[i] = idx >= 1024;
        int id = idx & 1023;
        srow[i] = id >> 3;  sc16[i] = id & 7;
    }

    auto load_chunk = [&](int kc, int st) {
        const uint32_t base = sbase + (uint32_t)st * STG_BB;
        const int kb = kc * 32;
#pragma unroll
        for (int i = 0; i < 8; i++) {
            uint32_t dst = base + (sisB[i] ? TILE_BB : 0)
                         + (uint32_t)(srow[i] * TROW_B + sc16[i] * 16);
            const float* src;
            if (sisB[i]) {
                src = g_wo + (col0 + srow[i]) * D_ + kb + sc16[i] * 4;
            } else {
                int row = row0 + srow[i];
                int b = row >> 11, s = row & (S_ - 1);
                int k = kb + sc16[i] * 4;
                int h = k >> 6, dk = k & 63;
                src = &g_ao[((b * H_ + h) * S_ + s) * DK_ + dk];
            }
            cpasync16(dst, src);
        }
        cpcommit();
    };

    float acc[4][4][4];
#pragma unroll
    for (int i = 0; i < 4; i++)
#pragma unroll
        for (int j = 0; j < 4; j++)
#pragma unroll
            for (int r = 0; r < 4; r++) acc[i][j][r] = 0.0f;

    load_chunk(0, 0);
    load_chunk(1, 1);

    for (int c = 0; c < NKT; c++) {
        const int st = c % 3;
        cpwait1();
        __syncthreads();
        if (c + 2 < NKT) load_chunk(c + 2, (c + 2) % 3);

        const uint32_t Ast = sbase + (uint32_t)st * STG_BB;
        const uint32_t Bst = Ast + TILE_BB;
#pragma unroll
        for (int ks = 0; ks < 4; ks++) {
            uint32_t a[4][4];
#pragma unroll
            for (int mf = 0; mf < 4; mf++)
                ldsm4(a[mf], Ast + (uint32_t)((wm + mf * 16) * TROW_B + ks * 32) + a_rl);
#pragma unroll
            for (int np = 0; np < 2; np++) {
                uint32_t bb[4];
                ldsm4(bb, Bst + (uint32_t)((wn + np * 16) * TROW_B + ks * 32) + b_rl);
#pragma unroll
                for (int mf = 0; mf < 4; mf++) {
                    mma8(acc[mf][np * 2 + 0], a[mf], bb);
                    mma8(acc[mf][np * 2 + 1], a[mf], bb + 2);
                }
            }
        }
    }

#pragma unroll
    for (int mf = 0; mf < 4; mf++) {
#pragma unroll
        for (int rr = 0; rr < 2; rr++) {
            int r = row0 + wm + mf * 16 + gr + rr * 8;
#pragma unroll
            for (int nf = 0; nf < 4; nf++) {
                int cc = col0 + wn + nf * 8 + 2 * tg;
                float2 v;
                v.x = acc[mf][nf][rr * 2 + 0] + bO[cc];
                v.y = acc[mf][nf][rr * 2 + 1] + bO[cc + 1];
                *(float2*)&out[r * D_ + cc] = v;
            }
        }
    }
}

// ============================================================================
// Kernel 2: causal flash attention — BQ=128, register softmax.
// K AND V b-fragments via ldmatrix.x4. V staged transposed ([dv][key], from
// g_vt) with stride 68 floats (272B): 16r mod 128 — conflict-free ldsm rows.
// ============================================================================
#define MASKV   (-3.0e38f)
#define QW      68
#define QWB     (QW * 4)                    // 272 B row stride (Q/K/V tiles)
#define QFL     (128 * QW)
#define KFL     (64 * QW)
#define VFL     (64 * QW)
#define KV_FL   (KFL + VFL)
#define ATTN_SMEM_BYTES ((QFL + 2 * KV_FL) * 4)

__global__ void __launch_bounds__(256)
attn_mma()
{
    extern __shared__ float dsm[];
    float* Qs = dsm;

    const int bh = blockIdx.x;
    const int qt = (gridDim.y - 1) - blockIdx.y;
    const float* __restrict__ Kp = g_qp + bh * S_ * DK_;
    const float* __restrict__ Qp = g_kp + bh * S_ * DK_;
    const float* __restrict__ Vt = g_vt + bh * DK_ * S_;   // [dk][s]
    float* __restrict__ Op = g_ao + bh * S_ * DK_;

    const int t    = threadIdx.x;
    const int lane = t & 31;
    const int wid  = t >> 5;
    const int gr   = lane >> 2;
    const int tg   = lane & 3;
    const int wr   = wid * 16;

    const uint32_t sbase = (uint32_t)__cvta_generic_to_shared(dsm);

    const int mi   = lane >> 3;
    const int lrow = lane & 7;
    const uint32_t kb_rl = (uint32_t)(((mi >> 1) * 8 + lrow) * QWB + (mi & 1) * 16);

    int cr[4], cc[4];
#pragma unroll
    for (int i = 0; i < 4; i++) {
        int f = t + i * 256;
        cr[i] = f >> 4;  cc[i] = (f & 15) * 4;
    }

    auto issue_kv = [&](int st, int kt) {
        const uint32_t sk = sbase + (uint32_t)(QFL + st * KV_FL) * 4u;
        const uint32_t sv = sk + (uint32_t)KFL * 4u;
#pragma unroll
        for (int i = 0; i < 4; i++)
            cpasync16(sk + (uint32_t)(cr[i] * QW + cc[i]) * 4u,
                      Kp + (kt * 64 + cr[i]) * DK_ + cc[i]);
        // V transposed tile: row = dv (0..63), cols = keys kt*64 + cc
#pragma unroll
        for (int i = 0; i < 4; i++)
            cpasync16(sv + (uint32_t)(cr[i] * QW + cc[i]) * 4u,
                      Vt + cr[i] * S_ + kt * 64 + cc[i]);
        cpcommit();
    };

    {
#pragma unroll
        for (int i = 0; i < 8; i++) {
            int f = t + i * 256;
            int r = f >> 4, c = (f & 15) * 4;
            cpasync16(sbase + (uint32_t)(r * QW + c) * 4u,
                      Qp + (qt * 128 + r) * DK_ + c);
        }
        issue_kv(0, 0);
    }
    cpwait0();
    __syncthreads();

    uint32_t qa[8][4];
#pragma unroll
    for (int ks = 0; ks < 8; ks++) {
        const int kk = ks * 8;
        qa[ks][0] = __float_as_uint(Qs[(wr + gr) * QW + kk + tg]);
        qa[ks][1] = __float_as_uint(Qs[(wr + gr + 8) * QW + kk + tg]);
        qa[ks][2] = __float_as_uint(Qs[(wr + gr) * QW + kk + tg + 4]);
        qa[ks][3] = __float_as_uint(Qs[(wr + gr + 8) * QW + kk + tg + 4]);
    }

    float o[8][4];
#pragma unroll
    for (int nf = 0; nf < 8; nf++)
#pragma unroll
        for (int r = 0; r < 4; r++) o[nf][r] = 0.0f;

    float m0 = MASKV, m1 = MASKV, l0 = 0.0f, l1 = 0.0f;
    const int ri0 = qt * 128 + wr + gr;
    const int ri1 = ri0 + 8;

    const int nkt = 2 * qt + 2;
    for (int kt = 0; kt < nkt; kt++) {
        const int st = kt & 1;
        const uint32_t KsAddr = sbase + (uint32_t)(QFL + st * KV_FL) * 4u;
        const uint32_t VsAddr = KsAddr + (uint32_t)KFL * 4u;

        cpwait0();
        __syncthreads();
        if (kt + 1 < nkt) issue_kv(st ^ 1, kt + 1);

        // ---- S = Q @ K^T (K b-frags via ldmatrix) ----
        float sc[8][4];
#pragma unroll
        for (int nf = 0; nf < 8; nf++)
#pragma unroll
            for (int r = 0; r < 4; r++) sc[nf][r] = 0.0f;

#pragma unroll
        for (int ks = 0; ks < 8; ks++) {
#pragma unroll
            for (int ng = 0; ng < 4; ng++) {
                uint32_t kb[4];
                ldsm4(kb, KsAddr + (uint32_t)(ng * 16) * QWB
                          + (uint32_t)(ks * 32) + kb_rl);
                mma8(sc[2 * ng + 0], qa[ks], kb);       // n = ng*16 + gr
                mma8(sc[2 * ng + 1], qa[ks], kb + 2);   // n = ng*16 + 8 + gr
            }
        }

        if (kt >= nkt - 2) {
#pragma unroll
            for (int nf = 0; nf < 8; nf++) {
                int c0 = kt * 64 + nf * 8 + 2 * tg;
                if (c0 > ri0)     sc[nf][0] = MASKV;
                if (c0 + 1 > ri0) sc[nf][1] = MASKV;
                if (c0 > ri1)     sc[nf][2] = MASKV;
                if (c0 + 1 > ri1) sc[nf][3] = MASKV;
            }
        }

        float tm0 = MASKV, tm1 = MASKV;
#pragma unroll
        for (int nf = 0; nf < 8; nf++) {
            tm0 = fmaxf(tm0, fmaxf(sc[nf][0], sc[nf][1]));
            tm1 = fmaxf(tm1, fmaxf(sc[nf][2], sc[nf][3]));
        }
        tm0 = fmaxf(tm0, __shfl_xor_sync(0xffffffffu, tm0, 1));
        tm0 = fmaxf(tm0, __shfl_xor_sync(0xffffffffu, tm0, 2));
        tm1 = fmaxf(tm1, __shfl_xor_sync(0xffffffffu, tm1, 1));
        tm1 = fmaxf(tm1, __shfl_xor_sync(0xffffffffu, tm1, 2));

        float m0n = fmaxf(m0, tm0), m1n = fmaxf(m1, tm1);
        float corr0 = __expf(m0 - m0n), corr1 = __expf(m1 - m1n);
        float ps0 = 0.0f, ps1 = 0.0f;
#pragma unroll
        for (int nf = 0; nf < 8; nf++) {
            float e0 = __expf(sc[nf][0] - m0n);
            float e1 = __expf(sc[nf][1] - m0n);
            float e2 = __expf(sc[nf][2] - m1n);
            float e3 = __expf(sc[nf][3] - m1n);
            ps0 += e0 + e1; ps1 += e2 + e3;
            sc[nf][0] = tf(e0); sc[nf][1] = tf(e1);
            sc[nf][2] = tf(e2); sc[nf][3] = tf(e3);
        }
        ps0 += __shfl_xor_sync(0xffffffffu, ps0, 1);
        ps0 += __shfl_xor_sync(0xffffffffu, ps0, 2);
        ps1 += __shfl_xor_sync(0xffffffffu, ps1, 1);
        ps1 += __shfl_xor_sync(0xffffffffu, ps1, 2);
        l0 = l0 * corr0 + ps0;  l1 = l1 * corr1 + ps1;
        m0 = m0n;  m1 = m1n;

#pragma unroll
        for (int nf = 0; nf < 8; nf++) {
            o[nf][0] *= corr0; o[nf][1] *= corr0;
            o[nf][2] *= corr1; o[nf][3] *= corr1;
        }

        // ---- O += P @ V (P via quad-shfl; V b-frags via ldmatrix on Vt) ----
        const int src1 = (lane & ~3) | (tg >> 1);
        const int src2 = src1 + 2;
        const int sel  = tg & 1;
#pragma unroll
        for (int ks = 0; ks < 8; ks++) {
            float v00 = __shfl_sync(0xffffffffu, sc[ks][0], src1);
            float v01 = __shfl_sync(0xffffffffu, sc[ks][1], src1);
            float v10 = __shfl_sync(0xffffffffu, sc[ks][2], src1);
            float v11 = __shfl_sync(0xffffffffu, sc[ks][3], src1);
            float w00 = __shfl_sync(0xffffffffu, sc[ks][0], src2);
            float w01 = __shfl_sync(0xffffffffu, sc[ks][1], src2);
            float w10 = __shfl_sync(0xffffffffu, sc[ks][2], src2);
            float w11 = __shfl_sync(0xffffffffu, sc[ks][3], src2);
            uint32_t a[4];
            a[0] = __float_as_uint(sel ? v01 : v00);
            a[1] = __float_as_uint(sel ? v11 : v10);
            a[2] = __float_as_uint(sel ? w01 : w00);
            a[3] = __float_as_uint(sel ? w11 : w10);
#pragma unroll
            for (int ng = 0; ng < 4; ng++) {
                uint32_t vb[4];
                ldsm4(vb, VsAddr + (uint32_t)(ng * 16) * QWB
                          + (uint32_t)(ks * 32) + kb_rl);
                mma8(o[2 * ng + 0], a, vb);         // n = ng*16 + gr
                mma8(o[2 * ng + 1], a, vb + 2);     // n = ng*16 + 8 + gr
            }
        }
    }

    const float li0 = 1.0f / l0, li1 = 1.0f / l1;
#pragma unroll
    for (int nf = 0; nf < 8; nf++) {
        int c = nf * 8 + 2 * tg;
        float2 v0, v1;
        v0.x = tf(o[nf][0] * li0); v0.y = tf(o[nf][1] * li0);
        v1.x = tf(o[nf][2] * li1); v1.y = tf(o[nf][3] * li1);
        *(float2*)&Op[ri0 * DK_ + c] = v0;
        *(float2*)&Op[ri1 * DK_ + c] = v1;
    }
}

// ============================================================================
// launcher — inputs: 0 X, 1 mask(unused), 2 WQ, 3 WK, 4 WV, 5 WO, 6 bO
// ============================================================================
extern "C" void kernel_launch(void* const* d_in, const int* in_sizes, int n_in,
                              void* d_out, int out_size)
{
    (void)in_sizes; (void)n_in; (void)out_size;
    const float* X  = (const float*)d_in[0];
    const float* WQ = (const float*)d_in[2];
    const float* WK = (const float*)d_in[3];
    const float* WV = (const float*)d_in[4];
    const float* WO = (const float*)d_in[5];
    const float* bO = (const float*)d_in[6];
    float* out = (float*)d_out;

    static bool s_init = false;
    if (!s_init) {
        cudaFuncSetAttribute(proj_qkv_mma,
                             cudaFuncAttributeMaxDynamicSharedMemorySize, GS_SMEM);
        cudaFuncSetAttribute(out_proj_mma,
                             cudaFuncAttributeMaxDynamicSharedMemorySize, GS_SMEM);
        cudaFuncSetAttribute(attn_mma,
                             cudaFuncAttributeMaxDynamicSharedMemorySize, ATTN_SMEM_BYTES);
        s_init = true;
    }

    x_round<<<2048, 256>>>(X);
    {
        dim3 grid(32, 32, 4);
        w_trans<<<grid, dim3(32, 8)>>>(WQ, WK, WV, WO);
    }
    {
        dim3 grid(8, 32, 3);
        proj_qkv_mma<<<grid, 256, GS_SMEM>>>();
    }
    {
        dim3 grid(BH_, S_ / 32, DK_ / 32);
        v_trans<<<grid, dim3(32, 8)>>>();
    }
    {
        dim3 grid(BH_, S_ / 128);
        attn_mma<<<grid, 256, ATTN_SMEM_BYTES>>>();
    }
    {
        dim3 grid(8, 32);
        out_proj_mma<<<grid, 256, GS_SMEM>>>(bO, out);
    }
}